// round 6
// baseline (speedup 1.0000x reference)
#include <cuda_runtime.h>
#include <cstdint>

#define NN      50000
#define NGRAPH  64
#define HID     128
#define NLAYERS 4
#define CAP     192     // per-node in-edge capacity (max expected in-degree ~45)

#define SA 132          // A tile row stride (floats): banks (4g+t) conflict-free
#define SMEM_BYTES (128 * SA * 4)     // 67584

// ---------------- scratch (no allocations allowed) ----------------
__device__ float    g_t[NN * HID];      // h @ W  (message source)
__device__ float    g_act[NN * HID];    // activation / aggregation buffer
__device__ int      g_srcs[NN * CAP];   // bucketed in-edge source lists
__device__ int      g_cursor[NN];       // in-degree (w/o self loop)
__device__ float    g_dinv[NN];         // rsqrt(deg)
__device__ uint32_t g_Whi[5 * HID * HID];  // tf32 hi parts of all 5 weights
__device__ uint32_t g_Wlo[5 * HID * HID];  // tf32 lo parts
__device__ float    g_pooled[NGRAPH * HID];
__device__ float    g_zero_bias[HID];   // stays all-zero
__device__ int      g_idx64;            // 1 if index buffers are int64

// ---------------- tf32 helpers -----------------------------------
__device__ __forceinline__ uint32_t f2tf32(float f) {
    uint32_t r;
    asm("cvt.rna.tf32.f32 %0, %1;" : "=r"(r) : "f"(f));
    return r;
}
__device__ __forceinline__ void split_tf32(float f, uint32_t& hi, uint32_t& lo) {
    hi = f2tf32(f);
    lo = f2tf32(f - __uint_as_float(hi));
}
__device__ __forceinline__ void mma_tf32(
    float& c0, float& c1, float& c2, float& c3,
    uint32_t a0, uint32_t a1, uint32_t a2, uint32_t a3,
    uint32_t b0, uint32_t b1)
{
    asm volatile(
        "mma.sync.aligned.m16n8k8.row.col.f32.tf32.tf32.f32 "
        "{%0,%1,%2,%3}, {%4,%5,%6,%7}, {%8,%9}, {%0,%1,%2,%3};"
        : "+f"(c0), "+f"(c1), "+f"(c2), "+f"(c3)
        : "r"(a0), "r"(a1), "r"(a2), "r"(a3), "r"(b0), "r"(b1));
}

// ---------------- dtype detection (warp-parallel) ----------------
__global__ void detect_dtype_kernel(const int* __restrict__ e) {
    int lane = threadIdx.x;
    int nz = 0;
    if (e[1 + 2 * lane] != 0) nz = 1;
    if (e[1 + 2 * (lane + 32)] != 0) nz = 1;
    unsigned m = __ballot_sync(0xFFFFFFFFu, nz);
    if (lane == 0) g_idx64 = (m == 0u) ? 1 : 0;
}

// ---------------- one-time weight split (5 x 128x128) -------------
__global__ void split_w_kernel(const float* __restrict__ W_in,
                               const float* __restrict__ conv_W) {
    int i = blockIdx.x * blockDim.x + threadIdx.x;
    if (i < 5 * HID * HID) {
        float v = (i < HID * HID) ? W_in[i] : conv_W[i - HID * HID];
        uint32_t hi, lo;
        split_tf32(v, hi, lo);
        g_Whi[i] = hi;
        g_Wlo[i] = lo;
    }
}

// ---------------- adjacency build --------------------------------
__global__ void zero_kernel(int n) {
    int i = blockIdx.x * blockDim.x + threadIdx.x;
    if (i < n) g_cursor[i] = 0;
}

__global__ void fill_kernel(const void* __restrict__ eidx, int E) {
    const int is64 = g_idx64;
    int i = blockIdx.x * blockDim.x + threadIdx.x;
    if (i < E) {
        int s, t;
        if (is64) {
            s = (int)((const long long*)eidx)[i];
            t = (int)((const long long*)eidx)[(long long)E + i];
        } else {
            s = ((const int*)eidx)[i];
            t = ((const int*)eidx)[E + i];
        }
        int p = atomicAdd(&g_cursor[t], 1);
        if (p < CAP) g_srcs[t * CAP + p] = s;
    }
}

__global__ void dinv_kernel(int n) {
    int i = blockIdx.x * blockDim.x + threadIdx.x;
    if (i < n) g_dinv[i] = rsqrtf((float)g_cursor[i] + 1.0f);
}

// ---------------- 3xTF32 tensor-core GEMM ------------------------
// C[M,128] = op(A)[M,128] @ W[128,128] (+ epi_bias)
//   PRO: op(a)[r][c] = relu(a[r][c] + pro_bias[c])
// A in smem (fp32, split in regs); B (pre-split tf32 hi/lo) streamed from
// global through L1. 256 threads = 8 warps (4M x 2N), warp tile 32x64.
template<bool PRO>
__global__ __launch_bounds__(256, 2) void gemm_kernel(
    const float* A, int widx,
    const float* __restrict__ pro_bias, const float* __restrict__ epi_bias,
    float* outC, int M)
{
    extern __shared__ float As[];     // [128][SA]

    const int tid = threadIdx.x;
    const int row0 = blockIdx.x * 128;

    // ---- load A tile (optional fused bias+relu) ----
#pragma unroll
    for (int l = 0; l < 16; l++) {
        int f = tid + l * 256;            // 0..4095 float4 slots
        int r = f >> 5;
        int c4 = f & 31;
        int grow = row0 + r;
        float4 v = make_float4(0.f, 0.f, 0.f, 0.f);
        if (grow < M) {
            v = *(const float4*)&A[(size_t)grow * 128 + c4 * 4];
            if (PRO) {
                float4 b = ((const float4*)pro_bias)[c4];
                v.x = fmaxf(v.x + b.x, 0.0f);
                v.y = fmaxf(v.y + b.y, 0.0f);
                v.z = fmaxf(v.z + b.z, 0.0f);
                v.w = fmaxf(v.w + b.w, 0.0f);
            }
        }
        *(float4*)&As[r * SA + c4 * 4] = v;
    }
    __syncthreads();

    const int warp = tid >> 5;
    const int lane = tid & 31;
    const int g = lane >> 2;          // 0..7
    const int t = lane & 3;           // 0..3
    const int wm = (warp >> 1) * 32;  // warp M offset
    const int wn = (warp & 1) * 64;   // warp N offset

    const uint32_t* __restrict__ Bh = g_Whi + (size_t)widx * HID * HID;
    const uint32_t* __restrict__ Bl = g_Wlo + (size_t)widx * HID * HID;

    float C[2][8][4];
#pragma unroll
    for (int i = 0; i < 2; i++)
#pragma unroll
        for (int j = 0; j < 8; j++)
#pragma unroll
            for (int q = 0; q < 4; q++) C[i][j][q] = 0.0f;

#pragma unroll
    for (int k8 = 0; k8 < 16; k8++) {
        const int k0 = k8 * 8;
        // A fragments (m16k8), 2 per warp tile; split hi/lo in regs
        uint32_t Ah[2][4], Al[2][4];
#pragma unroll
        for (int i = 0; i < 2; i++) {
            const int rb = wm + i * 16;
            split_tf32(As[(rb + g) * SA + k0 + t],     Ah[i][0], Al[i][0]);
            split_tf32(As[(rb + 8 + g) * SA + k0 + t], Ah[i][1], Al[i][1]);
            split_tf32(As[(rb + g) * SA + k0 + t + 4],     Ah[i][2], Al[i][2]);
            split_tf32(As[(rb + 8 + g) * SA + k0 + t + 4], Ah[i][3], Al[i][3]);
        }
#pragma unroll
        for (int j = 0; j < 8; j++) {
            const int n0 = wn + j * 8;
            uint32_t bh0 = __ldg(&Bh[(k0 + t) * HID + n0 + g]);
            uint32_t bh1 = __ldg(&Bh[(k0 + t + 4) * HID + n0 + g]);
            uint32_t bl0 = __ldg(&Bl[(k0 + t) * HID + n0 + g]);
            uint32_t bl1 = __ldg(&Bl[(k0 + t + 4) * HID + n0 + g]);
#pragma unroll
            for (int i = 0; i < 2; i++) {
                mma_tf32(C[i][j][0], C[i][j][1], C[i][j][2], C[i][j][3],
                         Ah[i][0], Ah[i][1], Ah[i][2], Ah[i][3], bh0, bh1);
                mma_tf32(C[i][j][0], C[i][j][1], C[i][j][2], C[i][j][3],
                         Ah[i][0], Ah[i][1], Ah[i][2], Ah[i][3], bl0, bl1);
                mma_tf32(C[i][j][0], C[i][j][1], C[i][j][2], C[i][j][3],
                         Al[i][0], Al[i][1], Al[i][2], Al[i][3], bh0, bh1);
            }
        }
    }

    // ---- epilogue ----
#pragma unroll
    for (int i = 0; i < 2; i++) {
#pragma unroll
        for (int j = 0; j < 8; j++) {
            const int col = wn + j * 8 + 2 * t;
            float be0 = 0.f, be1 = 0.f;
            if (epi_bias) { be0 = epi_bias[col]; be1 = epi_bias[col + 1]; }
            const int r0 = row0 + wm + i * 16 + g;
            const int r1 = r0 + 8;
            if (r0 < M) {
                float2 v = make_float2(C[i][j][0] + be0, C[i][j][1] + be1);
                *(float2*)&outC[(size_t)r0 * 128 + col] = v;
            }
            if (r1 < M) {
                float2 v = make_float2(C[i][j][2] + be0, C[i][j][3] + be1);
                *(float2*)&outC[(size_t)r1 * 128 + col] = v;
            }
        }
    }
}

// ---------------- pull aggregation: one block (128 thr) per node ---------
// act[n] = t[n]*dinv[n]^2 + sum_{s in in(n)} dinv[s]*dinv[n]*t[s]
__global__ __launch_bounds__(128) void gather_kernel(int N) {
    const int n = blockIdx.x;
    const int tid = threadIdx.x;
    __shared__ int   src_sm[CAP];
    __shared__ float w_sm[CAP];

    const int cnt = min(g_cursor[n], CAP);
    const float dn = g_dinv[n];

    for (int j = tid; j < cnt; j += 128) {
        int s = g_srcs[n * CAP + j];
        src_sm[j] = s;
        w_sm[j] = g_dinv[s] * dn;
    }
    __syncthreads();

    float a0 = g_t[(size_t)n * HID + tid] * (dn * dn);
    float a1 = 0.f, a2 = 0.f, a3 = 0.f;

    int j = 0;
    for (; j + 4 <= cnt; j += 4) {
        const float* p0 = g_t + (size_t)src_sm[j + 0] * HID + tid;
        const float* p1 = g_t + (size_t)src_sm[j + 1] * HID + tid;
        const float* p2 = g_t + (size_t)src_sm[j + 2] * HID + tid;
        const float* p3 = g_t + (size_t)src_sm[j + 3] * HID + tid;
        float v0 = __ldg(p0);
        float v1 = __ldg(p1);
        float v2 = __ldg(p2);
        float v3 = __ldg(p3);
        a0 = fmaf(w_sm[j + 0], v0, a0);
        a1 = fmaf(w_sm[j + 1], v1, a1);
        a2 = fmaf(w_sm[j + 2], v2, a2);
        a3 = fmaf(w_sm[j + 3], v3, a3);
    }
    for (; j < cnt; j++)
        a0 = fmaf(w_sm[j], __ldg(g_t + (size_t)src_sm[j] * HID + tid), a0);

    g_act[(size_t)n * HID + tid] = (a0 + a1) + (a2 + a3);
}

// ---------------- mean pool per graph (batch sorted), fused bias+relu ----
__device__ __forceinline__ int lower_bound_batch(const void* batch, int n, int val, int is64) {
    int lo = 0, hi = n;
    while (lo < hi) {
        int mid = (lo + hi) >> 1;
        long long b = is64 ? ((const long long*)batch)[mid]
                           : (long long)((const int*)batch)[mid];
        if (b < val) lo = mid + 1; else hi = mid;
    }
    return lo;
}

__global__ void pool_kernel(const void* __restrict__ batch,
                            const float* __restrict__ bias, int n) {
    const int g = blockIdx.x;
    const int tid = threadIdx.x;
    __shared__ int slo, shi;
    if (tid == 0) {
        int is64 = g_idx64;
        slo = lower_bound_batch(batch, n, g, is64);
        shi = lower_bound_batch(batch, n, g + 1, is64);
    }
    __syncthreads();
    const float b = bias[tid];
    float s0 = 0.f, s1 = 0.f, s2 = 0.f, s3 = 0.f;
    int lo = slo, hi = shi;
    int r = lo;
    for (; r + 4 <= hi; r += 4) {
        s0 += fmaxf(g_act[(size_t)(r + 0) * HID + tid] + b, 0.0f);
        s1 += fmaxf(g_act[(size_t)(r + 1) * HID + tid] + b, 0.0f);
        s2 += fmaxf(g_act[(size_t)(r + 2) * HID + tid] + b, 0.0f);
        s3 += fmaxf(g_act[(size_t)(r + 3) * HID + tid] + b, 0.0f);
    }
    for (; r < hi; r++)
        s0 += fmaxf(g_act[(size_t)r * HID + tid] + b, 0.0f);
    float sum = (s0 + s1) + (s2 + s3);
    float cnt = (float)(hi - lo);
    g_pooled[g * HID + tid] = sum / fmaxf(cnt, 1.0f);
}

// ---------------- heads --------------------------------------------------
__global__ void heads_kernel(
    const float* __restrict__ Wd, const float* __restrict__ bd,
    const float* __restrict__ Ws, const float* __restrict__ bsn,
    const float* __restrict__ Wr, const float* __restrict__ br,
    float* __restrict__ out)
{
    const int g = blockIdx.x;
    const int head = blockIdx.y;
    const int j = threadIdx.x;
    __shared__ float p[HID];
    p[j] = g_pooled[g * HID + j];
    __syncthreads();

    const float* W = (head == 0) ? Wd : (head == 1) ? Ws : Wr;
    const float* b = (head == 0) ? bd : (head == 1) ? bsn : br;
    float s = b[j];
#pragma unroll 8
    for (int k = 0; k < HID; k++)
        s = fmaf(p[k], W[k * HID + j], s);
    out[(size_t)head * NGRAPH * HID + g * HID + j] = s;
}

// ---------------- launch --------------------------------------------------
extern "C" void kernel_launch(void* const* d_in, const int* in_sizes, int n_in,
                              void* d_out, int out_size)
{
    const float* x      = (const float*)d_in[0];
    const void*  eidx   = d_in[1];
    const void*  batch  = d_in[2];
    const float* W_in   = (const float*)d_in[3];
    const float* b_in   = (const float*)d_in[4];
    const float* conv_W = (const float*)d_in[5];
    const float* conv_b = (const float*)d_in[6];
    const float* W_def  = (const float*)d_in[7];
    const float* b_def  = (const float*)d_in[8];
    const float* W_syn  = (const float*)d_in[9];
    const float* b_syn  = (const float*)d_in[10];
    const float* W_rel  = (const float*)d_in[11];
    const float* b_rel  = (const float*)d_in[12];
    float* out = (float*)d_out;

    const int N = in_sizes[0] / HID;       // 50000
    const int E = in_sizes[1] / 2;         // 640000

    void *pt, *pa, *pz;
    cudaGetSymbolAddress(&pt, g_t);
    cudaGetSymbolAddress(&pa, g_act);
    cudaGetSymbolAddress(&pz, g_zero_bias);
    float* t_buf   = (float*)pt;
    float* act_buf = (float*)pa;
    const float* zero_b = (const float*)pz;

    static int smem_set = 0;
    if (!smem_set) {
        cudaFuncSetAttribute(gemm_kernel<false>,
                             cudaFuncAttributeMaxDynamicSharedMemorySize, SMEM_BYTES);
        cudaFuncSetAttribute(gemm_kernel<true>,
                             cudaFuncAttributeMaxDynamicSharedMemorySize, SMEM_BYTES);
        smem_set = 1;
    }

    const int T = 256;
    const int GB = (N + 127) / 128;

    // 0. index dtype detection + weight split (independent of edges)
    detect_dtype_kernel<<<1, 32>>>((const int*)eidx);
    split_w_kernel<<<(5 * HID * HID + T - 1) / T, T>>>(W_in, conv_W);

    // 1. adjacency build
    zero_kernel<<<(N + T - 1) / T, T>>>(N);
    fill_kernel<<<(E + T - 1) / T, T>>>(eidx, E);
    dinv_kernel<<<(N + T - 1) / T, T>>>(N);

    // 2. input layer: act = x @ W_in + b_in (pre-activation)
    gemm_kernel<false><<<GB, 256, SMEM_BYTES>>>(x, 0, nullptr, b_in, act_buf, N);

    // 3. GCN layers: GEMM (relu+bias fused in prologue) then pull-gather
    for (int l = 0; l < NLAYERS; l++) {
        // l==0: b_in already added by input GEMM -> add zeros before relu
        const float* pro_b = (l == 0) ? zero_b : conv_b + (size_t)(l - 1) * HID;
        gemm_kernel<true><<<GB, 256, SMEM_BYTES>>>(
            act_buf, 1 + l, pro_b, nullptr, t_buf, N);
        gather_kernel<<<N, 128>>>(N);
    }

    // 4. global mean pool with fused final bias+relu
    pool_kernel<<<NGRAPH, HID>>>(batch, conv_b + (size_t)(NLAYERS - 1) * HID, N);

    // 5. output heads
    heads_kernel<<<dim3(NGRAPH, 3), HID>>>(W_def, b_def, W_syn, b_syn,
                                           W_rel, b_rel, out);
}

// round 7
// speedup vs baseline: 1.3641x; 1.3641x over previous
#include <cuda_runtime.h>
#include <cstdint>

#define NN      50000
#define NGRAPH  64
#define HID     128
#define NLAYERS 4
#define CAP     192     // per-node in-edge capacity (max expected in-degree ~45)

#define SA 132          // A tile row stride (floats): banks (4g+t) conflict-free
// smem: packed B frags (16 k8 * 16 jn * 32 lanes * 16B = 128KB) + A tile
#define BFRAG_PER_W (16 * 16 * 32)                 // 8192 uint4
#define SMEM_GEMM  (BFRAG_PER_W * 16 + 128 * SA * 4)   // 131072 + 67584 = 198656

// ---------------- scratch (no allocations allowed) ----------------
__device__ float    g_t[NN * HID];      // h @ W  (message source)
__device__ float    g_act[NN * HID];    // activation / aggregation buffer
__device__ int      g_srcs[NN * CAP];   // bucketed in-edge source lists
__device__ int      g_cursor[NN];       // in-degree (w/o self loop)
__device__ float    g_dinv[NN];         // rsqrt(deg)
__device__ uint4    g_Bfrag[5 * BFRAG_PER_W];  // fragment-packed tf32 hi/lo weights
__device__ float    g_pooled[NGRAPH * HID];
__device__ float    g_zero_bias[HID];   // stays all-zero
__device__ int      g_idx64;            // 1 if index buffers are int64

// ---------------- tf32 helpers -----------------------------------
__device__ __forceinline__ uint32_t f2tf32(float f) {
    uint32_t r;
    asm("cvt.rna.tf32.f32 %0, %1;" : "=r"(r) : "f"(f));
    return r;
}
__device__ __forceinline__ void split_tf32(float f, uint32_t& hi, uint32_t& lo) {
    hi = f2tf32(f);
    lo = f2tf32(f - __uint_as_float(hi));
}
__device__ __forceinline__ void mma_tf32(
    float& c0, float& c1, float& c2, float& c3,
    uint32_t a0, uint32_t a1, uint32_t a2, uint32_t a3,
    uint32_t b0, uint32_t b1)
{
    asm volatile(
        "mma.sync.aligned.m16n8k8.row.col.f32.tf32.tf32.f32 "
        "{%0,%1,%2,%3}, {%4,%5,%6,%7}, {%8,%9}, {%0,%1,%2,%3};"
        : "+f"(c0), "+f"(c1), "+f"(c2), "+f"(c3)
        : "r"(a0), "r"(a1), "r"(a2), "r"(a3), "r"(b0), "r"(b1));
}

// ---------------- dtype detection (warp-parallel) ----------------
__global__ void detect_dtype_kernel(const int* __restrict__ e) {
    int lane = threadIdx.x;
    int nz = 0;
    if (e[1 + 2 * lane] != 0) nz = 1;
    if (e[1 + 2 * (lane + 32)] != 0) nz = 1;
    unsigned m = __ballot_sync(0xFFFFFFFFu, nz);
    if (lane == 0) g_idx64 = (m == 0u) ? 1 : 0;
}

// ---------------- one-time weight split + fragment pack ------------------
// For weight w, k-block k8, n-block jn, lane (t=lane&3, g=lane>>2):
//   b0 = W[k8*8+t][jn*8+g], b1 = W[k8*8+t+4][jn*8+g]
// store uint4{hi(b0), hi(b1), lo(b0), lo(b1)}.
__global__ void pack_b_kernel(const float* __restrict__ W_in,
                              const float* __restrict__ conv_W) {
    int i = blockIdx.x * blockDim.x + threadIdx.x;
    if (i >= 5 * BFRAG_PER_W) return;
    int lane = i & 31;
    int jn   = (i >> 5) & 15;
    int k8   = (i >> 9) & 15;
    int w    = i >> 13;
    int t = lane & 3, g = lane >> 2;
    const float* W = (w == 0) ? W_in : conv_W + (size_t)(w - 1) * HID * HID;
    float b0 = W[(k8 * 8 + t) * HID + jn * 8 + g];
    float b1 = W[(k8 * 8 + t + 4) * HID + jn * 8 + g];
    uint32_t h0, l0, h1, l1;
    split_tf32(b0, h0, l0);
    split_tf32(b1, h1, l1);
    g_Bfrag[i] = make_uint4(h0, h1, l0, l1);
}

// ---------------- adjacency build --------------------------------
__global__ void zero_kernel(int n) {
    int i = blockIdx.x * blockDim.x + threadIdx.x;
    if (i < n) g_cursor[i] = 0;
}

__global__ void fill_kernel(const void* __restrict__ eidx, int E) {
    const int is64 = g_idx64;
    int i = blockIdx.x * blockDim.x + threadIdx.x;
    if (i < E) {
        int s, t;
        if (is64) {
            s = (int)((const long long*)eidx)[i];
            t = (int)((const long long*)eidx)[(long long)E + i];
        } else {
            s = ((const int*)eidx)[i];
            t = ((const int*)eidx)[E + i];
        }
        int p = atomicAdd(&g_cursor[t], 1);
        if (p < CAP) g_srcs[t * CAP + p] = s;
    }
}

__global__ void dinv_kernel(int n) {
    int i = blockIdx.x * blockDim.x + threadIdx.x;
    if (i < n) g_dinv[i] = rsqrtf((float)g_cursor[i] + 1.0f);
}

// ---------------- 3xTF32 tensor-core GEMM ------------------------
// C[M,128] = op(A)[M,128] @ W[128,128] (+ epi_bias)
//   PRO: op(a)[r][c] = relu(a[r][c] + pro_bias[c])
// 512 threads = 16 warps (8M x 2N), warp tile 16x64.
// A fp32 in smem (split in regs, 4/k8); B pre-split + fragment-packed in smem
// (one LDS.128 per j per k8, zero in-loop B ALU).
template<bool PRO>
__global__ __launch_bounds__(512, 1) void gemm_kernel(
    const float* A, int widx,
    const float* __restrict__ pro_bias, const float* __restrict__ epi_bias,
    float* outC, int M)
{
    extern __shared__ uint4 smem_u4[];
    uint4* Bs = smem_u4;                          // [16][16][32] uint4
    float* As = (float*)(smem_u4 + BFRAG_PER_W);  // [128][SA]

    const int tid = threadIdx.x;
    const int row0 = blockIdx.x * 128;

    // ---- load packed B frags (128KB) ----
    {
        const uint4* src = g_Bfrag + (size_t)widx * BFRAG_PER_W;
#pragma unroll
        for (int l = 0; l < BFRAG_PER_W / 512; l++)
            Bs[tid + l * 512] = src[tid + l * 512];
    }
    // ---- load A tile (optional fused bias+relu) ----
#pragma unroll
    for (int l = 0; l < 8; l++) {
        int f = tid + l * 512;            // 0..4095 float4 slots
        int r = f >> 5;
        int c4 = f & 31;
        int grow = row0 + r;
        float4 v = make_float4(0.f, 0.f, 0.f, 0.f);
        if (grow < M) {
            v = *(const float4*)&A[(size_t)grow * 128 + c4 * 4];
            if (PRO) {
                float4 b = ((const float4*)pro_bias)[c4];
                v.x = fmaxf(v.x + b.x, 0.0f);
                v.y = fmaxf(v.y + b.y, 0.0f);
                v.z = fmaxf(v.z + b.z, 0.0f);
                v.w = fmaxf(v.w + b.w, 0.0f);
            }
        }
        *(float4*)&As[r * SA + c4 * 4] = v;
    }
    __syncthreads();

    const int warp = tid >> 5;
    const int lane = tid & 31;
    const int g = lane >> 2;          // 0..7
    const int t = lane & 3;           // 0..3
    const int wm = (warp >> 1) * 16;  // warp M offset (8 warps cover 128)
    const int jnb = (warp & 1) * 8;   // warp N block offset (8 n-blocks of 8)

    float C[8][4];
#pragma unroll
    for (int j = 0; j < 8; j++)
#pragma unroll
        for (int q = 0; q < 4; q++) C[j][q] = 0.0f;

#pragma unroll
    for (int k8 = 0; k8 < 16; k8++) {
        const int k0 = k8 * 8;
        uint32_t Ah[4], Al[4];
        split_tf32(As[(wm + g) * SA + k0 + t],         Ah[0], Al[0]);
        split_tf32(As[(wm + 8 + g) * SA + k0 + t],     Ah[1], Al[1]);
        split_tf32(As[(wm + g) * SA + k0 + t + 4],     Ah[2], Al[2]);
        split_tf32(As[(wm + 8 + g) * SA + k0 + t + 4], Ah[3], Al[3]);
#pragma unroll
        for (int j = 0; j < 8; j++) {
            uint4 bf = Bs[(k8 * 16 + jnb + j) * 32 + lane];
            mma_tf32(C[j][0], C[j][1], C[j][2], C[j][3],
                     Ah[0], Ah[1], Ah[2], Ah[3], bf.x, bf.y);   // hi*hi
            mma_tf32(C[j][0], C[j][1], C[j][2], C[j][3],
                     Ah[0], Ah[1], Ah[2], Ah[3], bf.z, bf.w);   // hi*lo
            mma_tf32(C[j][0], C[j][1], C[j][2], C[j][3],
                     Al[0], Al[1], Al[2], Al[3], bf.x, bf.y);   // lo*hi
        }
    }

    // ---- epilogue ----
#pragma unroll
    for (int j = 0; j < 8; j++) {
        const int col = (jnb + j) * 8 + 2 * t;
        float be0 = 0.f, be1 = 0.f;
        if (epi_bias) { be0 = epi_bias[col]; be1 = epi_bias[col + 1]; }
        const int r0 = row0 + wm + g;
        const int r1 = r0 + 8;
        if (r0 < M) {
            float2 v = make_float2(C[j][0] + be0, C[j][1] + be1);
            *(float2*)&outC[(size_t)r0 * 128 + col] = v;
        }
        if (r1 < M) {
            float2 v = make_float2(C[j][2] + be0, C[j][3] + be1);
            *(float2*)&outC[(size_t)r1 * 128 + col] = v;
        }
    }
}

// ---------------- pull aggregation: one warp per target node -------------
// act[n] = t[n]*dinv[n]^2 + sum_{s in in(n)} dinv[s]*dinv[n]*t[s]
__global__ __launch_bounds__(256) void gather_kernel(int N) {
    const int warp = (int)((blockIdx.x * blockDim.x + threadIdx.x) >> 5);
    if (warp >= N) return;
    const int lane = threadIdx.x & 31;

    const int cnt = min(g_cursor[warp], CAP);
    const float dn = g_dinv[warp];

    float4 a0 = ((const float4*)(g_t + (size_t)warp * HID))[lane];
    const float s2 = dn * dn;
    a0.x *= s2; a0.y *= s2; a0.z *= s2; a0.w *= s2;
    float4 a1 = make_float4(0.f, 0.f, 0.f, 0.f);

    const int base = warp * CAP;
    for (int j0 = 0; j0 < cnt; j0 += 32) {
        const int m = min(32, cnt - j0);
        int   s_l = 0;
        float d_l = 0.f;
        if (lane < m) {
            s_l = g_srcs[base + j0 + lane];
            d_l = g_dinv[s_l] * dn;
        }
        int j = 0;
        for (; j + 2 <= m; j += 2) {
            int   sa = __shfl_sync(0xFFFFFFFFu, s_l, j);
            int   sb = __shfl_sync(0xFFFFFFFFu, s_l, j + 1);
            float na = __shfl_sync(0xFFFFFFFFu, d_l, j);
            float nb = __shfl_sync(0xFFFFFFFFu, d_l, j + 1);
            float4 va = ((const float4*)(g_t + (size_t)sa * HID))[lane];
            float4 vb = ((const float4*)(g_t + (size_t)sb * HID))[lane];
            a0.x = fmaf(na, va.x, a0.x); a0.y = fmaf(na, va.y, a0.y);
            a0.z = fmaf(na, va.z, a0.z); a0.w = fmaf(na, va.w, a0.w);
            a1.x = fmaf(nb, vb.x, a1.x); a1.y = fmaf(nb, vb.y, a1.y);
            a1.z = fmaf(nb, vb.z, a1.z); a1.w = fmaf(nb, vb.w, a1.w);
        }
        if (j < m) {
            int   sa = __shfl_sync(0xFFFFFFFFu, s_l, j);
            float na = __shfl_sync(0xFFFFFFFFu, d_l, j);
            float4 va = ((const float4*)(g_t + (size_t)sa * HID))[lane];
            a0.x = fmaf(na, va.x, a0.x); a0.y = fmaf(na, va.y, a0.y);
            a0.z = fmaf(na, va.z, a0.z); a0.w = fmaf(na, va.w, a0.w);
        }
    }
    a0.x += a1.x; a0.y += a1.y; a0.z += a1.z; a0.w += a1.w;
    ((float4*)(g_act + (size_t)warp * HID))[lane] = a0;
}

// ---------------- mean pool per graph (batch sorted), fused bias+relu ----
__device__ __forceinline__ int lower_bound_batch(const void* batch, int n, int val, int is64) {
    int lo = 0, hi = n;
    while (lo < hi) {
        int mid = (lo + hi) >> 1;
        long long b = is64 ? ((const long long*)batch)[mid]
                           : (long long)((const int*)batch)[mid];
        if (b < val) lo = mid + 1; else hi = mid;
    }
    return lo;
}

__global__ void pool_kernel(const void* __restrict__ batch,
                            const float* __restrict__ bias, int n) {
    const int g = blockIdx.x;
    const int tid = threadIdx.x;
    __shared__ int slo, shi;
    if (tid == 0) {
        int is64 = g_idx64;
        slo = lower_bound_batch(batch, n, g, is64);
        shi = lower_bound_batch(batch, n, g + 1, is64);
    }
    __syncthreads();
    const float b = bias[tid];
    float s0 = 0.f, s1 = 0.f, s2 = 0.f, s3 = 0.f;
    int lo = slo, hi = shi;
    int r = lo;
    for (; r + 4 <= hi; r += 4) {
        s0 += fmaxf(g_act[(size_t)(r + 0) * HID + tid] + b, 0.0f);
        s1 += fmaxf(g_act[(size_t)(r + 1) * HID + tid] + b, 0.0f);
        s2 += fmaxf(g_act[(size_t)(r + 2) * HID + tid] + b, 0.0f);
        s3 += fmaxf(g_act[(size_t)(r + 3) * HID + tid] + b, 0.0f);
    }
    for (; r < hi; r++)
        s0 += fmaxf(g_act[(size_t)r * HID + tid] + b, 0.0f);
    float sum = (s0 + s1) + (s2 + s3);
    float cnt = (float)(hi - lo);
    g_pooled[g * HID + tid] = sum / fmaxf(cnt, 1.0f);
}

// ---------------- heads --------------------------------------------------
__global__ void heads_kernel(
    const float* __restrict__ Wd, const float* __restrict__ bd,
    const float* __restrict__ Ws, const float* __restrict__ bsn,
    const float* __restrict__ Wr, const float* __restrict__ br,
    float* __restrict__ out)
{
    const int g = blockIdx.x;
    const int head = blockIdx.y;
    const int j = threadIdx.x;
    __shared__ float p[HID];
    p[j] = g_pooled[g * HID + j];
    __syncthreads();

    const float* W = (head == 0) ? Wd : (head == 1) ? Ws : Wr;
    const float* b = (head == 0) ? bd : (head == 1) ? bsn : br;
    float s = b[j];
#pragma unroll 8
    for (int k = 0; k < HID; k++)
        s = fmaf(p[k], W[k * HID + j], s);
    out[(size_t)head * NGRAPH * HID + g * HID + j] = s;
}

// ---------------- launch --------------------------------------------------
extern "C" void kernel_launch(void* const* d_in, const int* in_sizes, int n_in,
                              void* d_out, int out_size)
{
    const float* x      = (const float*)d_in[0];
    const void*  eidx   = d_in[1];
    const void*  batch  = d_in[2];
    const float* W_in   = (const float*)d_in[3];
    const float* b_in   = (const float*)d_in[4];
    const float* conv_W = (const float*)d_in[5];
    const float* conv_b = (const float*)d_in[6];
    const float* W_def  = (const float*)d_in[7];
    const float* b_def  = (const float*)d_in[8];
    const float* W_syn  = (const float*)d_in[9];
    const float* b_syn  = (const float*)d_in[10];
    const float* W_rel  = (const float*)d_in[11];
    const float* b_rel  = (const float*)d_in[12];
    float* out = (float*)d_out;

    const int N = in_sizes[0] / HID;       // 50000
    const int E = in_sizes[1] / 2;         // 640000

    void *pt, *pa, *pz;
    cudaGetSymbolAddress(&pt, g_t);
    cudaGetSymbolAddress(&pa, g_act);
    cudaGetSymbolAddress(&pz, g_zero_bias);
    float* t_buf   = (float*)pt;
    float* act_buf = (float*)pa;
    const float* zero_b = (const float*)pz;

    static int smem_set = 0;
    if (!smem_set) {
        cudaFuncSetAttribute(gemm_kernel<false>,
                             cudaFuncAttributeMaxDynamicSharedMemorySize, SMEM_GEMM);
        cudaFuncSetAttribute(gemm_kernel<true>,
                             cudaFuncAttributeMaxDynamicSharedMemorySize, SMEM_GEMM);
        smem_set = 1;
    }

    const int T = 256;
    const int GB = (N + 127) / 128;

    // 0. index dtype detection + weight split/pack (independent of edges)
    detect_dtype_kernel<<<1, 32>>>((const int*)eidx);
    pack_b_kernel<<<(5 * BFRAG_PER_W + T - 1) / T, T>>>(W_in, conv_W);

    // 1. adjacency build
    zero_kernel<<<(N + T - 1) / T, T>>>(N);
    fill_kernel<<<(E + T - 1) / T, T>>>(eidx, E);
    dinv_kernel<<<(N + T - 1) / T, T>>>(N);

    // 2. input layer: act = x @ W_in + b_in (pre-activation)
    gemm_kernel<false><<<GB, 512, SMEM_GEMM>>>(x, 0, nullptr, b_in, act_buf, N);

    // 3. GCN layers: GEMM (relu+bias fused in prologue) then pull-gather
    for (int l = 0; l < NLAYERS; l++) {
        // l==0: b_in already added by input GEMM -> add zeros before relu
        const float* pro_b = (l == 0) ? zero_b : conv_b + (size_t)(l - 1) * HID;
        gemm_kernel<true><<<GB, 512, SMEM_GEMM>>>(
            act_buf, 1 + l, pro_b, nullptr, t_buf, N);
        gather_kernel<<<(N * 32 + T - 1) / T, T>>>(N);
    }

    // 4. global mean pool with fused final bias+relu
    pool_kernel<<<NGRAPH, HID>>>(batch, conv_b + (size_t)(NLAYERS - 1) * HID, N);

    // 5. output heads
    heads_kernel<<<dim3(NGRAPH, 3), HID>>>(W_def, b_def, W_syn, b_syn,
                                           W_rel, b_rel, out);
}

// round 8
// speedup vs baseline: 1.4617x; 1.0715x over previous
#include <cuda_runtime.h>
#include <cstdint>

#define NN      50000
#define NGRAPH  64
#define HID     128
#define NLAYERS 4
#define CAP     192     // per-node in-edge capacity (max expected in-degree ~45)
#define NSUB    16      // pool sub-slices per graph

#define SA 132          // A tile row stride (floats): banks (4g+t) conflict-free
#define BFRAG_PER_W (16 * 16 * 32)                 // 8192 uint4
#define SMEM_GEMM  (BFRAG_PER_W * 16 + 128 * SA * 4)   // 198656

// ---------------- scratch (no allocations allowed) ----------------
__device__ float    g_t[NN * HID];      // h @ W  (message source)
__device__ float    g_act[NN * HID];    // activation / aggregation buffer
__device__ int      g_srcs[NN * CAP];   // bucketed in-edge source lists
__device__ float    g_w[NN * CAP];      // precomputed per-edge norm weights
__device__ int      g_cursor[NN];       // in-degree (w/o self loop)
__device__ float    g_dinv[NN];         // rsqrt(deg)
__device__ uint4    g_Bfrag[5 * BFRAG_PER_W];  // fragment-packed tf32 hi/lo weights
__device__ float    g_pooled[NGRAPH * HID];
__device__ float    g_cnt[NGRAPH];
__device__ float    g_zero_bias[HID];   // stays all-zero
__device__ int      g_idx64;            // 1 if index buffers are int64

// ---------------- tf32 helpers -----------------------------------
__device__ __forceinline__ uint32_t f2tf32(float f) {
    uint32_t r;
    asm("cvt.rna.tf32.f32 %0, %1;" : "=r"(r) : "f"(f));
    return r;
}
__device__ __forceinline__ void split_tf32(float f, uint32_t& hi, uint32_t& lo) {
    hi = f2tf32(f);
    lo = f2tf32(f - __uint_as_float(hi));
}
__device__ __forceinline__ void mma_tf32(
    float& c0, float& c1, float& c2, float& c3,
    uint32_t a0, uint32_t a1, uint32_t a2, uint32_t a3,
    uint32_t b0, uint32_t b1)
{
    asm volatile(
        "mma.sync.aligned.m16n8k8.row.col.f32.tf32.tf32.f32 "
        "{%0,%1,%2,%3}, {%4,%5,%6,%7}, {%8,%9}, {%0,%1,%2,%3};"
        : "+f"(c0), "+f"(c1), "+f"(c2), "+f"(c3)
        : "r"(a0), "r"(a1), "r"(a2), "r"(a3), "r"(b0), "r"(b1));
}

// ---------------- dtype detection (warp-parallel) ----------------
__global__ void detect_dtype_kernel(const int* __restrict__ e) {
    int lane = threadIdx.x;
    int nz = 0;
    if (e[1 + 2 * lane] != 0) nz = 1;
    if (e[1 + 2 * (lane + 32)] != 0) nz = 1;
    unsigned m = __ballot_sync(0xFFFFFFFFu, nz);
    if (lane == 0) g_idx64 = (m == 0u) ? 1 : 0;
}

// ---------------- one-time weight split + fragment pack ------------------
__global__ void pack_b_kernel(const float* __restrict__ W_in,
                              const float* __restrict__ conv_W) {
    int i = blockIdx.x * blockDim.x + threadIdx.x;
    if (i >= 5 * BFRAG_PER_W) return;
    int lane = i & 31;
    int jn   = (i >> 5) & 15;
    int k8   = (i >> 9) & 15;
    int w    = i >> 13;
    int t = lane & 3, g = lane >> 2;
    const float* W = (w == 0) ? W_in : conv_W + (size_t)(w - 1) * HID * HID;
    float b0 = W[(k8 * 8 + t) * HID + jn * 8 + g];
    float b1 = W[(k8 * 8 + t + 4) * HID + jn * 8 + g];
    uint32_t h0, l0, h1, l1;
    split_tf32(b0, h0, l0);
    split_tf32(b1, h1, l1);
    g_Bfrag[i] = make_uint4(h0, h1, l0, l1);
}

// ---------------- adjacency build --------------------------------
__global__ void zero_kernel(int n) {
    int i = blockIdx.x * blockDim.x + threadIdx.x;
    if (i < n) g_cursor[i] = 0;
    if (i < NGRAPH * HID) g_pooled[i] = 0.0f;
}

__global__ void fill_kernel(const void* __restrict__ eidx, int E) {
    const int is64 = g_idx64;
    int i = blockIdx.x * blockDim.x + threadIdx.x;
    if (i < E) {
        int s, t;
        if (is64) {
            s = (int)((const long long*)eidx)[i];
            t = (int)((const long long*)eidx)[(long long)E + i];
        } else {
            s = ((const int*)eidx)[i];
            t = ((const int*)eidx)[E + i];
        }
        int p = atomicAdd(&g_cursor[t], 1);
        if (p < CAP) g_srcs[t * CAP + p] = s;
    }
}

__global__ void dinv_kernel(int n) {
    int i = blockIdx.x * blockDim.x + threadIdx.x;
    if (i < n) g_dinv[i] = rsqrtf((float)g_cursor[i] + 1.0f);
}

// ---- per-edge weights, once: g_w[n*CAP+j] = dinv[src]*dinv[n] ----
__global__ __launch_bounds__(256) void edge_w_kernel(int N) {
    const int n = (int)((blockIdx.x * blockDim.x + threadIdx.x) >> 5);
    if (n >= N) return;
    const int lane = threadIdx.x & 31;
    const int cnt = min(g_cursor[n], CAP);
    const float dn = g_dinv[n];
    for (int j = lane; j < cnt; j += 32)
        g_w[n * CAP + j] = g_dinv[g_srcs[n * CAP + j]] * dn;
}

// ---------------- 3xTF32 tensor-core GEMM ------------------------
// C[M,128] = op(A)[M,128] @ W[128,128] (+ epi_bias)
//   PRO: op(a)[r][c] = relu(a[r][c] + pro_bias[c])
// 512 threads = 16 warps (8M x 2N), warp tile 16x64.
template<bool PRO>
__global__ __launch_bounds__(512, 1) void gemm_kernel(
    const float* A, int widx,
    const float* __restrict__ pro_bias, const float* __restrict__ epi_bias,
    float* outC, int M)
{
    extern __shared__ uint4 smem_u4[];
    uint4* Bs = smem_u4;                          // [16][16][32] uint4
    float* As = (float*)(smem_u4 + BFRAG_PER_W);  // [128][SA]

    const int tid = threadIdx.x;
    const int row0 = blockIdx.x * 128;

    {
        const uint4* src = g_Bfrag + (size_t)widx * BFRAG_PER_W;
#pragma unroll
        for (int l = 0; l < BFRAG_PER_W / 512; l++)
            Bs[tid + l * 512] = src[tid + l * 512];
    }
#pragma unroll
    for (int l = 0; l < 8; l++) {
        int f = tid + l * 512;
        int r = f >> 5;
        int c4 = f & 31;
        int grow = row0 + r;
        float4 v = make_float4(0.f, 0.f, 0.f, 0.f);
        if (grow < M) {
            v = *(const float4*)&A[(size_t)grow * 128 + c4 * 4];
            if (PRO) {
                float4 b = ((const float4*)pro_bias)[c4];
                v.x = fmaxf(v.x + b.x, 0.0f);
                v.y = fmaxf(v.y + b.y, 0.0f);
                v.z = fmaxf(v.z + b.z, 0.0f);
                v.w = fmaxf(v.w + b.w, 0.0f);
            }
        }
        *(float4*)&As[r * SA + c4 * 4] = v;
    }
    __syncthreads();

    const int warp = tid >> 5;
    const int lane = tid & 31;
    const int g = lane >> 2;
    const int t = lane & 3;
    const int wm = (warp >> 1) * 16;
    const int jnb = (warp & 1) * 8;

    float C[8][4];
#pragma unroll
    for (int j = 0; j < 8; j++)
#pragma unroll
        for (int q = 0; q < 4; q++) C[j][q] = 0.0f;

#pragma unroll
    for (int k8 = 0; k8 < 16; k8++) {
        const int k0 = k8 * 8;
        uint32_t Ah[4], Al[4];
        split_tf32(As[(wm + g) * SA + k0 + t],         Ah[0], Al[0]);
        split_tf32(As[(wm + 8 + g) * SA + k0 + t],     Ah[1], Al[1]);
        split_tf32(As[(wm + g) * SA + k0 + t + 4],     Ah[2], Al[2]);
        split_tf32(As[(wm + 8 + g) * SA + k0 + t + 4], Ah[3], Al[3]);
#pragma unroll
        for (int j = 0; j < 8; j++) {
            uint4 bf = Bs[(k8 * 16 + jnb + j) * 32 + lane];
            mma_tf32(C[j][0], C[j][1], C[j][2], C[j][3],
                     Ah[0], Ah[1], Ah[2], Ah[3], bf.x, bf.y);
            mma_tf32(C[j][0], C[j][1], C[j][2], C[j][3],
                     Ah[0], Ah[1], Ah[2], Ah[3], bf.z, bf.w);
            mma_tf32(C[j][0], C[j][1], C[j][2], C[j][3],
                     Al[0], Al[1], Al[2], Al[3], bf.x, bf.y);
        }
    }

#pragma unroll
    for (int j = 0; j < 8; j++) {
        const int col = (jnb + j) * 8 + 2 * t;
        float be0 = 0.f, be1 = 0.f;
        if (epi_bias) { be0 = epi_bias[col]; be1 = epi_bias[col + 1]; }
        const int r0 = row0 + wm + g;
        const int r1 = r0 + 8;
        if (r0 < M) {
            float2 v = make_float2(C[j][0] + be0, C[j][1] + be1);
            *(float2*)&outC[(size_t)r0 * 128 + col] = v;
        }
        if (r1 < M) {
            float2 v = make_float2(C[j][2] + be0, C[j][3] + be1);
            *(float2*)&outC[(size_t)r1 * 128 + col] = v;
        }
    }
}

// ---------------- pull aggregation: one warp per node, ILP-4 -------------
// act[n] = t[n]*dinv[n]^2 + sum_{s in in(n)} w * t[s]
__global__ __launch_bounds__(256) void gather_kernel(int N) {
    const int n = (int)((blockIdx.x * blockDim.x + threadIdx.x) >> 5);
    if (n >= N) return;
    const int lane = threadIdx.x & 31;

    const int cnt = min(g_cursor[n], CAP);
    const float dn = g_dinv[n];

    float4 a0 = ((const float4*)(g_t + (size_t)n * HID))[lane];
    const float s2 = dn * dn;
    a0.x *= s2; a0.y *= s2; a0.z *= s2; a0.w *= s2;
    float4 a1 = make_float4(0.f, 0.f, 0.f, 0.f);
    float4 a2 = make_float4(0.f, 0.f, 0.f, 0.f);
    float4 a3 = make_float4(0.f, 0.f, 0.f, 0.f);

    const int base = n * CAP;
    for (int j0 = 0; j0 < cnt; j0 += 32) {
        const int m = min(32, cnt - j0);
        int   s_l = 0;
        float w_l = 0.f;
        if (lane < m) {
            s_l = g_srcs[base + j0 + lane];
            w_l = g_w[base + j0 + lane];
        }
        int j = 0;
        for (; j + 4 <= m; j += 4) {
            int   sa = __shfl_sync(0xFFFFFFFFu, s_l, j);
            int   sb = __shfl_sync(0xFFFFFFFFu, s_l, j + 1);
            int   sc = __shfl_sync(0xFFFFFFFFu, s_l, j + 2);
            int   sd = __shfl_sync(0xFFFFFFFFu, s_l, j + 3);
            float na = __shfl_sync(0xFFFFFFFFu, w_l, j);
            float nb = __shfl_sync(0xFFFFFFFFu, w_l, j + 1);
            float nc = __shfl_sync(0xFFFFFFFFu, w_l, j + 2);
            float nd = __shfl_sync(0xFFFFFFFFu, w_l, j + 3);
            float4 va = __ldg(&((const float4*)(g_t + (size_t)sa * HID))[lane]);
            float4 vb = __ldg(&((const float4*)(g_t + (size_t)sb * HID))[lane]);
            float4 vc = __ldg(&((const float4*)(g_t + (size_t)sc * HID))[lane]);
            float4 vd = __ldg(&((const float4*)(g_t + (size_t)sd * HID))[lane]);
            a0.x = fmaf(na, va.x, a0.x); a0.y = fmaf(na, va.y, a0.y);
            a0.z = fmaf(na, va.z, a0.z); a0.w = fmaf(na, va.w, a0.w);
            a1.x = fmaf(nb, vb.x, a1.x); a1.y = fmaf(nb, vb.y, a1.y);
            a1.z = fmaf(nb, vb.z, a1.z); a1.w = fmaf(nb, vb.w, a1.w);
            a2.x = fmaf(nc, vc.x, a2.x); a2.y = fmaf(nc, vc.y, a2.y);
            a2.z = fmaf(nc, vc.z, a2.z); a2.w = fmaf(nc, vc.w, a2.w);
            a3.x = fmaf(nd, vd.x, a3.x); a3.y = fmaf(nd, vd.y, a3.y);
            a3.z = fmaf(nd, vd.z, a3.z); a3.w = fmaf(nd, vd.w, a3.w);
        }
        for (; j < m; j++) {
            int   sa = __shfl_sync(0xFFFFFFFFu, s_l, j);
            float na = __shfl_sync(0xFFFFFFFFu, w_l, j);
            float4 va = __ldg(&((const float4*)(g_t + (size_t)sa * HID))[lane]);
            a0.x = fmaf(na, va.x, a0.x); a0.y = fmaf(na, va.y, a0.y);
            a0.z = fmaf(na, va.z, a0.z); a0.w = fmaf(na, va.w, a0.w);
        }
    }
    a0.x += a1.x + a2.x + a3.x;
    a0.y += a1.y + a2.y + a3.y;
    a0.z += a1.z + a2.z + a3.z;
    a0.w += a1.w + a2.w + a3.w;
    ((float4*)(g_act + (size_t)n * HID))[lane] = a0;
}

// ---------------- mean pool, 2-stage (batch sorted), fused bias+relu -----
__device__ __forceinline__ int lower_bound_batch(const void* batch, int n, int val, int is64) {
    int lo = 0, hi = n;
    while (lo < hi) {
        int mid = (lo + hi) >> 1;
        long long b = is64 ? ((const long long*)batch)[mid]
                           : (long long)((const int*)batch)[mid];
        if (b < val) lo = mid + 1; else hi = mid;
    }
    return lo;
}

__global__ void pool_partial_kernel(const void* __restrict__ batch,
                                    const float* __restrict__ bias, int n) {
    const int g = blockIdx.x;
    const int sub = blockIdx.y;
    const int tid = threadIdx.x;
    __shared__ int slo, shi;
    if (tid == 0) {
        int is64 = g_idx64;
        slo = lower_bound_batch(batch, n, g, is64);
        shi = lower_bound_batch(batch, n, g + 1, is64);
    }
    __syncthreads();
    const float b = bias[tid];
    const int lo = slo, hi = shi;
    float s0 = 0.f, s1 = 0.f;
    int r = lo + sub;
    for (; r + NSUB < hi; r += 2 * NSUB) {
        s0 += fmaxf(__ldg(&g_act[(size_t)r * HID + tid]) + b, 0.0f);
        s1 += fmaxf(__ldg(&g_act[(size_t)(r + NSUB) * HID + tid]) + b, 0.0f);
    }
    if (r < hi)
        s0 += fmaxf(__ldg(&g_act[(size_t)r * HID + tid]) + b, 0.0f);
    atomicAdd(&g_pooled[g * HID + tid], s0 + s1);
    if (sub == 0 && tid == 0) g_cnt[g] = (float)(hi - lo);
}

// ---------------- heads (divide pooled sum by count here) ----------------
__global__ void heads_kernel(
    const float* __restrict__ Wd, const float* __restrict__ bd,
    const float* __restrict__ Ws, const float* __restrict__ bsn,
    const float* __restrict__ Wr, const float* __restrict__ br,
    float* __restrict__ out)
{
    const int g = blockIdx.x;
    const int head = blockIdx.y;
    const int j = threadIdx.x;
    __shared__ float p[HID];
    const float inv = 1.0f / fmaxf(g_cnt[g], 1.0f);
    p[j] = g_pooled[g * HID + j] * inv;
    __syncthreads();

    const float* W = (head == 0) ? Wd : (head == 1) ? Ws : Wr;
    const float* b = (head == 0) ? bd : (head == 1) ? bsn : br;
    float s = b[j];
#pragma unroll 8
    for (int k = 0; k < HID; k++)
        s = fmaf(p[k], W[k * HID + j], s);
    out[(size_t)head * NGRAPH * HID + g * HID + j] = s;
}

// ---------------- launch --------------------------------------------------
extern "C" void kernel_launch(void* const* d_in, const int* in_sizes, int n_in,
                              void* d_out, int out_size)
{
    const float* x      = (const float*)d_in[0];
    const void*  eidx   = d_in[1];
    const void*  batch  = d_in[2];
    const float* W_in   = (const float*)d_in[3];
    const float* b_in   = (const float*)d_in[4];
    const float* conv_W = (const float*)d_in[5];
    const float* conv_b = (const float*)d_in[6];
    const float* W_def  = (const float*)d_in[7];
    const float* b_def  = (const float*)d_in[8];
    const float* W_syn  = (const float*)d_in[9];
    const float* b_syn  = (const float*)d_in[10];
    const float* W_rel  = (const float*)d_in[11];
    const float* b_rel  = (const float*)d_in[12];
    float* out = (float*)d_out;

    const int N = in_sizes[0] / HID;       // 50000
    const int E = in_sizes[1] / 2;         // 640000

    void *pt, *pa, *pz;
    cudaGetSymbolAddress(&pt, g_t);
    cudaGetSymbolAddress(&pa, g_act);
    cudaGetSymbolAddress(&pz, g_zero_bias);
    float* t_buf   = (float*)pt;
    float* act_buf = (float*)pa;
    const float* zero_b = (const float*)pz;

    static int smem_set = 0;
    if (!smem_set) {
        cudaFuncSetAttribute(gemm_kernel<false>,
                             cudaFuncAttributeMaxDynamicSharedMemorySize, SMEM_GEMM);
        cudaFuncSetAttribute(gemm_kernel<true>,
                             cudaFuncAttributeMaxDynamicSharedMemorySize, SMEM_GEMM);
        smem_set = 1;
    }

    const int T = 256;
    const int GB = (N + 127) / 128;
    const int GW = (N * 32 + T - 1) / T;   // warp-per-node grids

    // 0. index dtype detection + weight split/pack
    detect_dtype_kernel<<<1, 32>>>((const int*)eidx);
    pack_b_kernel<<<(5 * BFRAG_PER_W + T - 1) / T, T>>>(W_in, conv_W);

    // 1. adjacency build (+ zero pooled accumulators)
    zero_kernel<<<(N + T - 1) / T, T>>>(N);
    fill_kernel<<<(E + T - 1) / T, T>>>(eidx, E);
    dinv_kernel<<<(N + T - 1) / T, T>>>(N);
    edge_w_kernel<<<GW, T>>>(N);

    // 2. input layer: act = x @ W_in + b_in (pre-activation)
    gemm_kernel<false><<<GB, 512, SMEM_GEMM>>>(x, 0, nullptr, b_in, act_buf, N);

    // 3. GCN layers
    for (int l = 0; l < NLAYERS; l++) {
        const float* pro_b = (l == 0) ? zero_b : conv_b + (size_t)(l - 1) * HID;
        gemm_kernel<true><<<GB, 512, SMEM_GEMM>>>(
            act_buf, 1 + l, pro_b, nullptr, t_buf, N);
        gather_kernel<<<GW, T>>>(N);
    }

    // 4. global mean pool (2-stage, fused final bias+relu)
    pool_partial_kernel<<<dim3(NGRAPH, NSUB), HID>>>(
        batch, conv_b + (size_t)(NLAYERS - 1) * HID, N);

    // 5. output heads
    heads_kernel<<<dim3(NGRAPH, 3), HID>>>(W_def, b_def, W_syn, b_syn,
                                           W_rel, b_rel, out);
}

// round 9
// speedup vs baseline: 1.5376x; 1.0519x over previous
#include <cuda_runtime.h>
#include <cuda_bf16.h>
#include <cstdint>

#define NN      50000
#define NGRAPH  64
#define HID     128
#define NLAYERS 4
#define CAP     192     // per-node in-edge capacity (max expected in-degree ~45)
#define NSUB    16      // pool sub-slices per graph

#define SA 132          // A tile row stride (floats): banks (4g+t) conflict-free
#define BFRAG_PER_W (16 * 16 * 32)                 // 8192 uint4
#define SMEM_GEMM  (BFRAG_PER_W * 16 + 128 * SA * 4)   // 198656

// ---------------- scratch (no allocations allowed) ----------------
__device__ __nv_bfloat162 g_tb[NN * (HID / 2)];  // bf16 messages (h @ W)
__device__ float    g_act[NN * HID];    // activation / aggregation buffer (fp32)
__device__ int      g_srcs[NN * CAP];   // bucketed in-edge source lists
__device__ float    g_w[NN * CAP];      // precomputed per-edge norm weights
__device__ int      g_cursor[NN];       // in-degree (w/o self loop)
__device__ float    g_dinv[NN];         // rsqrt(deg)
__device__ uint4    g_Bfrag[5 * BFRAG_PER_W];  // fragment-packed tf32 hi/lo weights
__device__ float    g_pooled[NGRAPH * HID];
__device__ float    g_cnt[NGRAPH];
__device__ float    g_zero_bias[HID];   // stays all-zero
__device__ int      g_idx64;            // 1 if index buffers are int64

// ---------------- tf32 helpers -----------------------------------
__device__ __forceinline__ uint32_t f2tf32(float f) {
    uint32_t r;
    asm("cvt.rna.tf32.f32 %0, %1;" : "=r"(r) : "f"(f));
    return r;
}
__device__ __forceinline__ void split_tf32(float f, uint32_t& hi, uint32_t& lo) {
    hi = f2tf32(f);
    lo = f2tf32(f - __uint_as_float(hi));
}
__device__ __forceinline__ void mma_tf32(
    float& c0, float& c1, float& c2, float& c3,
    uint32_t a0, uint32_t a1, uint32_t a2, uint32_t a3,
    uint32_t b0, uint32_t b1)
{
    asm volatile(
        "mma.sync.aligned.m16n8k8.row.col.f32.tf32.tf32.f32 "
        "{%0,%1,%2,%3}, {%4,%5,%6,%7}, {%8,%9}, {%0,%1,%2,%3};"
        : "+f"(c0), "+f"(c1), "+f"(c2), "+f"(c3)
        : "r"(a0), "r"(a1), "r"(a2), "r"(a3), "r"(b0), "r"(b1));
}

// ---------------- dtype detection (warp-parallel) ----------------
__global__ void detect_dtype_kernel(const int* __restrict__ e) {
    int lane = threadIdx.x;
    int nz = 0;
    if (e[1 + 2 * lane] != 0) nz = 1;
    if (e[1 + 2 * (lane + 32)] != 0) nz = 1;
    unsigned m = __ballot_sync(0xFFFFFFFFu, nz);
    if (lane == 0) g_idx64 = (m == 0u) ? 1 : 0;
}

// ---------------- one-time weight split + fragment pack ------------------
__global__ void pack_b_kernel(const float* __restrict__ W_in,
                              const float* __restrict__ conv_W) {
    int i = blockIdx.x * blockDim.x + threadIdx.x;
    if (i >= 5 * BFRAG_PER_W) return;
    int lane = i & 31;
    int jn   = (i >> 5) & 15;
    int k8   = (i >> 9) & 15;
    int w    = i >> 13;
    int t = lane & 3, g = lane >> 2;
    const float* W = (w == 0) ? W_in : conv_W + (size_t)(w - 1) * HID * HID;
    float b0 = W[(k8 * 8 + t) * HID + jn * 8 + g];
    float b1 = W[(k8 * 8 + t + 4) * HID + jn * 8 + g];
    uint32_t h0, l0, h1, l1;
    split_tf32(b0, h0, l0);
    split_tf32(b1, h1, l1);
    g_Bfrag[i] = make_uint4(h0, h1, l0, l1);
}

// ---------------- adjacency build --------------------------------
__global__ void zero_kernel(int n) {
    int i = blockIdx.x * blockDim.x + threadIdx.x;
    if (i < n) g_cursor[i] = 0;
    if (i < NGRAPH * HID) g_pooled[i] = 0.0f;
}

__global__ void fill_kernel(const void* __restrict__ eidx, int E) {
    const int is64 = g_idx64;
    int i = blockIdx.x * blockDim.x + threadIdx.x;
    if (i < E) {
        int s, t;
        if (is64) {
            s = (int)((const long long*)eidx)[i];
            t = (int)((const long long*)eidx)[(long long)E + i];
        } else {
            s = ((const int*)eidx)[i];
            t = ((const int*)eidx)[E + i];
        }
        int p = atomicAdd(&g_cursor[t], 1);
        if (p < CAP) g_srcs[t * CAP + p] = s;
    }
}

__global__ void dinv_kernel(int n) {
    int i = blockIdx.x * blockDim.x + threadIdx.x;
    if (i < n) g_dinv[i] = rsqrtf((float)g_cursor[i] + 1.0f);
}

// ---- per-edge weights, once: g_w[n*CAP+j] = dinv[src]*dinv[n] ----
__global__ __launch_bounds__(256) void edge_w_kernel(int N) {
    const int n = (int)((blockIdx.x * blockDim.x + threadIdx.x) >> 5);
    if (n >= N) return;
    const int lane = threadIdx.x & 31;
    const int cnt = min(g_cursor[n], CAP);
    const float dn = g_dinv[n];
    for (int j = lane; j < cnt; j += 32)
        g_w[n * CAP + j] = g_dinv[g_srcs[n * CAP + j]] * dn;
}

// ---------------- 3xTF32 tensor-core GEMM ------------------------
// C[M,128] = op(A)[M,128] @ W[128,128]
//   PRO:   op(a)[r][c] = relu(a[r][c] + pro_bias[c])
//   BFOUT: write bf16x2 to g_tb (no epi bias); else fp32 (+epi_bias) to outC
// 512 threads = 16 warps (8M x 2N), warp tile 16x64.
template<bool PRO, bool BFOUT>
__global__ __launch_bounds__(512, 1) void gemm_kernel(
    const float* A, int widx,
    const float* __restrict__ pro_bias, const float* __restrict__ epi_bias,
    float* outC, int M)
{
    extern __shared__ uint4 smem_u4[];
    uint4* Bs = smem_u4;                          // [16][16][32] uint4
    float* As = (float*)(smem_u4 + BFRAG_PER_W);  // [128][SA]

    const int tid = threadIdx.x;
    const int row0 = blockIdx.x * 128;

    {
        const uint4* src = g_Bfrag + (size_t)widx * BFRAG_PER_W;
#pragma unroll
        for (int l = 0; l < BFRAG_PER_W / 512; l++)
            Bs[tid + l * 512] = src[tid + l * 512];
    }
#pragma unroll
    for (int l = 0; l < 8; l++) {
        int f = tid + l * 512;
        int r = f >> 5;
        int c4 = f & 31;
        int grow = row0 + r;
        float4 v = make_float4(0.f, 0.f, 0.f, 0.f);
        if (grow < M) {
            v = *(const float4*)&A[(size_t)grow * 128 + c4 * 4];
            if (PRO) {
                float4 b = ((const float4*)pro_bias)[c4];
                v.x = fmaxf(v.x + b.x, 0.0f);
                v.y = fmaxf(v.y + b.y, 0.0f);
                v.z = fmaxf(v.z + b.z, 0.0f);
                v.w = fmaxf(v.w + b.w, 0.0f);
            }
        }
        *(float4*)&As[r * SA + c4 * 4] = v;
    }
    __syncthreads();

    const int warp = tid >> 5;
    const int lane = tid & 31;
    const int g = lane >> 2;
    const int t = lane & 3;
    const int wm = (warp >> 1) * 16;
    const int jnb = (warp & 1) * 8;

    float C[8][4];
#pragma unroll
    for (int j = 0; j < 8; j++)
#pragma unroll
        for (int q = 0; q < 4; q++) C[j][q] = 0.0f;

#pragma unroll
    for (int k8 = 0; k8 < 16; k8++) {
        const int k0 = k8 * 8;
        uint32_t Ah[4], Al[4];
        split_tf32(As[(wm + g) * SA + k0 + t],         Ah[0], Al[0]);
        split_tf32(As[(wm + 8 + g) * SA + k0 + t],     Ah[1], Al[1]);
        split_tf32(As[(wm + g) * SA + k0 + t + 4],     Ah[2], Al[2]);
        split_tf32(As[(wm + 8 + g) * SA + k0 + t + 4], Ah[3], Al[3]);
#pragma unroll
        for (int j = 0; j < 8; j++) {
            uint4 bf = Bs[(k8 * 16 + jnb + j) * 32 + lane];
            mma_tf32(C[j][0], C[j][1], C[j][2], C[j][3],
                     Ah[0], Ah[1], Ah[2], Ah[3], bf.x, bf.y);
            mma_tf32(C[j][0], C[j][1], C[j][2], C[j][3],
                     Ah[0], Ah[1], Ah[2], Ah[3], bf.z, bf.w);
            mma_tf32(C[j][0], C[j][1], C[j][2], C[j][3],
                     Al[0], Al[1], Al[2], Al[3], bf.x, bf.y);
        }
    }

#pragma unroll
    for (int j = 0; j < 8; j++) {
        const int col = (jnb + j) * 8 + 2 * t;
        const int r0 = row0 + wm + g;
        const int r1 = r0 + 8;
        if (BFOUT) {
            if (r0 < M)
                g_tb[(size_t)r0 * (HID / 2) + (col >> 1)] =
                    __float22bfloat162_rn(make_float2(C[j][0], C[j][1]));
            if (r1 < M)
                g_tb[(size_t)r1 * (HID / 2) + (col >> 1)] =
                    __float22bfloat162_rn(make_float2(C[j][2], C[j][3]));
        } else {
            float be0 = 0.f, be1 = 0.f;
            if (epi_bias) { be0 = epi_bias[col]; be1 = epi_bias[col + 1]; }
            if (r0 < M) {
                float2 v = make_float2(C[j][0] + be0, C[j][1] + be1);
                *(float2*)&outC[(size_t)r0 * 128 + col] = v;
            }
            if (r1 < M) {
                float2 v = make_float2(C[j][2] + be0, C[j][3] + be1);
                *(float2*)&outC[(size_t)r1 * 128 + col] = v;
            }
        }
    }
}

// ---------------- pull aggregation: one warp per node, ILP-4, bf16 msgs --
// act[n] = t[n]*dinv[n]^2 + sum_{s in in(n)} w * t[s]
__device__ __forceinline__ float4 ld_msg(int row, int lane) {
    uint2 u = __ldg(&((const uint2*)g_tb)[(size_t)row * 32 + lane]);
    float2 f0 = __bfloat1622float2(*(__nv_bfloat162*)&u.x);
    float2 f1 = __bfloat1622float2(*(__nv_bfloat162*)&u.y);
    return make_float4(f0.x, f0.y, f1.x, f1.y);
}

__global__ __launch_bounds__(256) void gather_kernel(int N) {
    const int n = (int)((blockIdx.x * blockDim.x + threadIdx.x) >> 5);
    if (n >= N) return;
    const int lane = threadIdx.x & 31;

    const int cnt = min(g_cursor[n], CAP);
    const float dn = g_dinv[n];

    float4 a0 = ld_msg(n, lane);
    const float s2 = dn * dn;
    a0.x *= s2; a0.y *= s2; a0.z *= s2; a0.w *= s2;
    float4 a1 = make_float4(0.f, 0.f, 0.f, 0.f);
    float4 a2 = make_float4(0.f, 0.f, 0.f, 0.f);
    float4 a3 = make_float4(0.f, 0.f, 0.f, 0.f);

    const int base = n * CAP;
    for (int j0 = 0; j0 < cnt; j0 += 32) {
        const int m = min(32, cnt - j0);
        int   s_l = 0;
        float w_l = 0.f;
        if (lane < m) {
            s_l = g_srcs[base + j0 + lane];
            w_l = g_w[base + j0 + lane];
        }
        int j = 0;
        for (; j + 4 <= m; j += 4) {
            int   sa = __shfl_sync(0xFFFFFFFFu, s_l, j);
            int   sb = __shfl_sync(0xFFFFFFFFu, s_l, j + 1);
            int   sc = __shfl_sync(0xFFFFFFFFu, s_l, j + 2);
            int   sd = __shfl_sync(0xFFFFFFFFu, s_l, j + 3);
            float na = __shfl_sync(0xFFFFFFFFu, w_l, j);
            float nb = __shfl_sync(0xFFFFFFFFu, w_l, j + 1);
            float nc = __shfl_sync(0xFFFFFFFFu, w_l, j + 2);
            float nd = __shfl_sync(0xFFFFFFFFu, w_l, j + 3);
            float4 va = ld_msg(sa, lane);
            float4 vb = ld_msg(sb, lane);
            float4 vc = ld_msg(sc, lane);
            float4 vd = ld_msg(sd, lane);
            a0.x = fmaf(na, va.x, a0.x); a0.y = fmaf(na, va.y, a0.y);
            a0.z = fmaf(na, va.z, a0.z); a0.w = fmaf(na, va.w, a0.w);
            a1.x = fmaf(nb, vb.x, a1.x); a1.y = fmaf(nb, vb.y, a1.y);
            a1.z = fmaf(nb, vb.z, a1.z); a1.w = fmaf(nb, vb.w, a1.w);
            a2.x = fmaf(nc, vc.x, a2.x); a2.y = fmaf(nc, vc.y, a2.y);
            a2.z = fmaf(nc, vc.z, a2.z); a2.w = fmaf(nc, vc.w, a2.w);
            a3.x = fmaf(nd, vd.x, a3.x); a3.y = fmaf(nd, vd.y, a3.y);
            a3.z = fmaf(nd, vd.z, a3.z); a3.w = fmaf(nd, vd.w, a3.w);
        }
        for (; j < m; j++) {
            int   sa = __shfl_sync(0xFFFFFFFFu, s_l, j);
            float na = __shfl_sync(0xFFFFFFFFu, w_l, j);
            float4 va = ld_msg(sa, lane);
            a0.x = fmaf(na, va.x, a0.x); a0.y = fmaf(na, va.y, a0.y);
            a0.z = fmaf(na, va.z, a0.z); a0.w = fmaf(na, va.w, a0.w);
        }
    }
    a0.x += a1.x + a2.x + a3.x;
    a0.y += a1.y + a2.y + a3.y;
    a0.z += a1.z + a2.z + a3.z;
    a0.w += a1.w + a2.w + a3.w;
    ((float4*)(g_act + (size_t)n * HID))[lane] = a0;
}

// ---------------- mean pool, 2-stage (batch sorted), fused bias+relu -----
__device__ __forceinline__ int lower_bound_batch(const void* batch, int n, int val, int is64) {
    int lo = 0, hi = n;
    while (lo < hi) {
        int mid = (lo + hi) >> 1;
        long long b = is64 ? ((const long long*)batch)[mid]
                           : (long long)((const int*)batch)[mid];
        if (b < val) lo = mid + 1; else hi = mid;
    }
    return lo;
}

__global__ void pool_partial_kernel(const void* __restrict__ batch,
                                    const float* __restrict__ bias, int n) {
    const int g = blockIdx.x;
    const int sub = blockIdx.y;
    const int tid = threadIdx.x;
    __shared__ int slo, shi;
    if (tid == 0) {
        int is64 = g_idx64;
        slo = lower_bound_batch(batch, n, g, is64);
        shi = lower_bound_batch(batch, n, g + 1, is64);
    }
    __syncthreads();
    const float b = bias[tid];
    const int lo = slo, hi = shi;
    float s0 = 0.f, s1 = 0.f;
    int r = lo + sub;
    for (; r + NSUB < hi; r += 2 * NSUB) {
        s0 += fmaxf(__ldg(&g_act[(size_t)r * HID + tid]) + b, 0.0f);
        s1 += fmaxf(__ldg(&g_act[(size_t)(r + NSUB) * HID + tid]) + b, 0.0f);
    }
    if (r < hi)
        s0 += fmaxf(__ldg(&g_act[(size_t)r * HID + tid]) + b, 0.0f);
    atomicAdd(&g_pooled[g * HID + tid], s0 + s1);
    if (sub == 0 && tid == 0) g_cnt[g] = (float)(hi - lo);
}

// ---------------- heads (divide pooled sum by count here) ----------------
__global__ void heads_kernel(
    const float* __restrict__ Wd, const float* __restrict__ bd,
    const float* __restrict__ Ws, const float* __restrict__ bsn,
    const float* __restrict__ Wr, const float* __restrict__ br,
    float* __restrict__ out)
{
    const int g = blockIdx.x;
    const int head = blockIdx.y;
    const int j = threadIdx.x;
    __shared__ float p[HID];
    const float inv = 1.0f / fmaxf(g_cnt[g], 1.0f);
    p[j] = g_pooled[g * HID + j] * inv;
    __syncthreads();

    const float* W = (head == 0) ? Wd : (head == 1) ? Ws : Wr;
    const float* b = (head == 0) ? bd : (head == 1) ? bsn : br;
    float s = b[j];
#pragma unroll 8
    for (int k = 0; k < HID; k++)
        s = fmaf(p[k], W[k * HID + j], s);
    out[(size_t)head * NGRAPH * HID + g * HID + j] = s;
}

// ---------------- launch --------------------------------------------------
extern "C" void kernel_launch(void* const* d_in, const int* in_sizes, int n_in,
                              void* d_out, int out_size)
{
    const float* x      = (const float*)d_in[0];
    const void*  eidx   = d_in[1];
    const void*  batch  = d_in[2];
    const float* W_in   = (const float*)d_in[3];
    const float* b_in   = (const float*)d_in[4];
    const float* conv_W = (const float*)d_in[5];
    const float* conv_b = (const float*)d_in[6];
    const float* W_def  = (const float*)d_in[7];
    const float* b_def  = (const float*)d_in[8];
    const float* W_syn  = (const float*)d_in[9];
    const float* b_syn  = (const float*)d_in[10];
    const float* W_rel  = (const float*)d_in[11];
    const float* b_rel  = (const float*)d_in[12];
    float* out = (float*)d_out;

    const int N = in_sizes[0] / HID;       // 50000
    const int E = in_sizes[1] / 2;         // 640000

    void *pa, *pz;
    cudaGetSymbolAddress(&pa, g_act);
    cudaGetSymbolAddress(&pz, g_zero_bias);
    float* act_buf = (float*)pa;
    const float* zero_b = (const float*)pz;

    static int smem_set = 0;
    if (!smem_set) {
        cudaFuncSetAttribute((const void*)gemm_kernel<false, false>,
                             cudaFuncAttributeMaxDynamicSharedMemorySize, SMEM_GEMM);
        cudaFuncSetAttribute((const void*)gemm_kernel<true, true>,
                             cudaFuncAttributeMaxDynamicSharedMemorySize, SMEM_GEMM);
        smem_set = 1;
    }

    const int T = 256;
    const int GB = (N + 127) / 128;
    const int GW = (N * 32 + T - 1) / T;   // warp-per-node grids

    // 0. index dtype detection + weight split/pack
    detect_dtype_kernel<<<1, 32>>>((const int*)eidx);
    pack_b_kernel<<<(5 * BFRAG_PER_W + T - 1) / T, T>>>(W_in, conv_W);

    // 1. adjacency build (+ zero pooled accumulators)
    zero_kernel<<<(N + T - 1) / T, T>>>(N);
    fill_kernel<<<(E + T - 1) / T, T>>>(eidx, E);
    dinv_kernel<<<(N + T - 1) / T, T>>>(N);
    edge_w_kernel<<<GW, T>>>(N);

    // 2. input layer: act = x @ W_in + b_in (fp32 pre-activation)
    gemm_kernel<false, false><<<GB, 512, SMEM_GEMM>>>(
        x, 0, nullptr, b_in, act_buf, N);

    // 3. GCN layers: GEMM (relu+bias fused, bf16 out) then pull-gather
    for (int l = 0; l < NLAYERS; l++) {
        const float* pro_b = (l == 0) ? zero_b : conv_b + (size_t)(l - 1) * HID;
        gemm_kernel<true, true><<<GB, 512, SMEM_GEMM>>>(
            act_buf, 1 + l, pro_b, nullptr, nullptr, N);
        gather_kernel<<<GW, T>>>(N);
    }

    // 4. global mean pool (2-stage, fused final bias+relu)
    pool_partial_kernel<<<dim3(NGRAPH, NSUB), HID>>>(
        batch, conv_b + (size_t)(NLAYERS - 1) * HID, N);

    // 5. output heads
    heads_kernel<<<dim3(NGRAPH, 3), HID>>>(W_def, b_def, W_syn, b_syn,
                                           W_rel, b_rel, out);
}

// round 11
// speedup vs baseline: 1.6835x; 1.0949x over previous
#include <cuda_runtime.h>
#include <cuda_bf16.h>
#include <cstdint>

#define NN      50000
#define NGRAPH  64
#define HID     128
#define NLAYERS 4
#define CAP     192     // per-node in-edge capacity (max expected in-degree ~45)
#define NSUB    16      // pool sub-slices per graph

#define SA 132          // A tile row stride (floats): banks (4g+t) conflict-free
#define BFRAG_PER_W (16 * 16 * 32)                 // 8192 uint4
#define SMEM_GEMM  (BFRAG_PER_W * 16 + 128 * SA * 4)   // 198656

// ---------------- scratch (no allocations allowed) ----------------
__device__ __nv_bfloat162 g_tb[NN * (HID / 2)];  // bf16 messages (h @ W)
__device__ float    g_act[NN * HID];    // activation / aggregation buffer (fp32)
__device__ int      g_srcs[NN * CAP];   // bucketed in-edge source lists
__device__ float    g_w[NN * CAP];      // precomputed per-edge norm weights
__device__ int      g_cursor[NN];       // in-degree (w/o self loop)
__device__ uint4    g_Bfrag[5 * BFRAG_PER_W];  // fragment-packed tf32 hi/lo weights
__device__ float    g_pooled[NGRAPH * HID];
__device__ float    g_cnt[NGRAPH];
__device__ float    g_zero_bias[HID];   // stays all-zero
__device__ int      g_idx64;            // 1 if index buffers are int64

// ---------------- tf32 helpers -----------------------------------
__device__ __forceinline__ uint32_t f2tf32(float f) {
    uint32_t r;
    asm("cvt.rna.tf32.f32 %0, %1;" : "=r"(r) : "f"(f));
    return r;
}
__device__ __forceinline__ void split_tf32(float f, uint32_t& hi, uint32_t& lo) {
    hi = f2tf32(f);
    lo = f2tf32(f - __uint_as_float(hi));
}
__device__ __forceinline__ void mma_tf32(
    float& c0, float& c1, float& c2, float& c3,
    uint32_t a0, uint32_t a1, uint32_t a2, uint32_t a3,
    uint32_t b0, uint32_t b1)
{
    asm volatile(
        "mma.sync.aligned.m16n8k8.row.col.f32.tf32.tf32.f32 "
        "{%0,%1,%2,%3}, {%4,%5,%6,%7}, {%8,%9}, {%0,%1,%2,%3};"
        : "+f"(c0), "+f"(c1), "+f"(c2), "+f"(c3)
        : "r"(a0), "r"(a1), "r"(a2), "r"(a3), "r"(b0), "r"(b1));
}

// ---------------- dtype detection (warp-parallel) ----------------
__global__ void detect_dtype_kernel(const int* __restrict__ e) {
    int lane = threadIdx.x;
    int nz = 0;
    if (e[1 + 2 * lane] != 0) nz = 1;
    if (e[1 + 2 * (lane + 32)] != 0) nz = 1;
    unsigned m = __ballot_sync(0xFFFFFFFFu, nz);
    if (lane == 0) g_idx64 = (m == 0u) ? 1 : 0;
}

// ---------------- one-time weight split + fragment pack ------------------
__global__ void pack_b_kernel(const float* __restrict__ W_in,
                              const float* __restrict__ conv_W) {
    int i = blockIdx.x * blockDim.x + threadIdx.x;
    if (i >= 5 * BFRAG_PER_W) return;
    int lane = i & 31;
    int jn   = (i >> 5) & 15;
    int k8   = (i >> 9) & 15;
    int w    = i >> 13;
    int t = lane & 3, g = lane >> 2;
    const float* W = (w == 0) ? W_in : conv_W + (size_t)(w - 1) * HID * HID;
    float b0 = W[(k8 * 8 + t) * HID + jn * 8 + g];
    float b1 = W[(k8 * 8 + t + 4) * HID + jn * 8 + g];
    uint32_t h0, l0, h1, l1;
    split_tf32(b0, h0, l0);
    split_tf32(b1, h1, l1);
    g_Bfrag[i] = make_uint4(h0, h1, l0, l1);
}

// ---------------- adjacency build --------------------------------
__global__ void zero_kernel(int n) {
    int i = blockIdx.x * blockDim.x + threadIdx.x;
    if (i < n) g_cursor[i] = 0;
    if (i < NGRAPH * HID) g_pooled[i] = 0.0f;
}

__global__ void fill_kernel(const void* __restrict__ eidx, int E) {
    const int is64 = g_idx64;
    int i = blockIdx.x * blockDim.x + threadIdx.x;
    if (i < E) {
        int s, t;
        if (is64) {
            s = (int)((const long long*)eidx)[i];
            t = (int)((const long long*)eidx)[(long long)E + i];
        } else {
            s = ((const int*)eidx)[i];
            t = ((const int*)eidx)[E + i];
        }
        int p = atomicAdd(&g_cursor[t], 1);
        if (p < CAP) g_srcs[t * CAP + p] = s;
    }
}

// ---- per-edge weights, once: g_w[n*CAP+j] = dinv[src]*dinv[n] ----
__global__ __launch_bounds__(256) void edge_w_kernel(int N) {
    const int n = (int)((blockIdx.x * blockDim.x + threadIdx.x) >> 5);
    if (n >= N) return;
    const int lane = threadIdx.x & 31;
    const int cnt = min(g_cursor[n], CAP);
    const float dn = rsqrtf((float)cnt + 1.0f);
    for (int j = lane; j < cnt; j += 32) {
        int s = g_srcs[n * CAP + j];
        g_w[n * CAP + j] = rsqrtf((float)min(g_cursor[s], CAP) + 1.0f) * dn;
    }
}

// ---------------- 3xTF32 tensor-core GEMM ------------------------
// C[M,128] = op(A)[M,128] @ W[128,128]
//   PRO:   op(a)[r][c] = relu(a[r][c] + pro_bias[c])
//   BFOUT: write bf16x2 to g_tb; else fp32 (+epi_bias) to outC
// 512 threads = 16 warps (8M x 2N), warp tile 16x64.
template<bool PRO, bool BFOUT>
__global__ __launch_bounds__(512, 1) void gemm_kernel(
    const float* A, int widx,
    const float* __restrict__ pro_bias, const float* __restrict__ epi_bias,
    float* outC, int M)
{
    extern __shared__ uint4 smem_u4[];
    uint4* Bs = smem_u4;                          // [16][16][32] uint4
    float* As = (float*)(smem_u4 + BFRAG_PER_W);  // [128][SA]

    const int tid = threadIdx.x;
    const int row0 = blockIdx.x * 128;

    {
        const uint4* src = g_Bfrag + (size_t)widx * BFRAG_PER_W;
#pragma unroll
        for (int l = 0; l < BFRAG_PER_W / 512; l++)
            Bs[tid + l * 512] = src[tid + l * 512];
    }
#pragma unroll
    for (int l = 0; l < 8; l++) {
        int f = tid + l * 512;
        int r = f >> 5;
        int c4 = f & 31;
        int grow = row0 + r;
        float4 v = make_float4(0.f, 0.f, 0.f, 0.f);
        if (grow < M) {
            v = *(const float4*)&A[(size_t)grow * 128 + c4 * 4];
            if (PRO) {
                float4 b = ((const float4*)pro_bias)[c4];
                v.x = fmaxf(v.x + b.x, 0.0f);
                v.y = fmaxf(v.y + b.y, 0.0f);
                v.z = fmaxf(v.z + b.z, 0.0f);
                v.w = fmaxf(v.w + b.w, 0.0f);
            }
        }
        *(float4*)&As[r * SA + c4 * 4] = v;
    }
    __syncthreads();

    const int warp = tid >> 5;
    const int lane = tid & 31;
    const int g = lane >> 2;
    const int t = lane & 3;
    const int wm = (warp >> 1) * 16;
    const int jnb = (warp & 1) * 8;

    float C[8][4];
#pragma unroll
    for (int j = 0; j < 8; j++)
#pragma unroll
        for (int q = 0; q < 4; q++) C[j][q] = 0.0f;

#pragma unroll
    for (int k8 = 0; k8 < 16; k8++) {
        const int k0 = k8 * 8;
        uint32_t Ah[4], Al[4];
        split_tf32(As[(wm + g) * SA + k0 + t],         Ah[0], Al[0]);
        split_tf32(As[(wm + 8 + g) * SA + k0 + t],     Ah[1], Al[1]);
        split_tf32(As[(wm + g) * SA + k0 + t + 4],     Ah[2], Al[2]);
        split_tf32(As[(wm + 8 + g) * SA + k0 + t + 4], Ah[3], Al[3]);
#pragma unroll
        for (int j = 0; j < 8; j++) {
            uint4 bf = Bs[(k8 * 16 + jnb + j) * 32 + lane];
            mma_tf32(C[j][0], C[j][1], C[j][2], C[j][3],
                     Ah[0], Ah[1], Ah[2], Ah[3], bf.x, bf.y);
            mma_tf32(C[j][0], C[j][1], C[j][2], C[j][3],
                     Ah[0], Ah[1], Ah[2], Ah[3], bf.z, bf.w);
            mma_tf32(C[j][0], C[j][1], C[j][2], C[j][3],
                     Al[0], Al[1], Al[2], Al[3], bf.x, bf.y);
        }
    }

#pragma unroll
    for (int j = 0; j < 8; j++) {
        const int col = (jnb + j) * 8 + 2 * t;
        const int r0 = row0 + wm + g;
        const int r1 = r0 + 8;
        if (BFOUT) {
            if (r0 < M)
                g_tb[(size_t)r0 * (HID / 2) + (col >> 1)] =
                    __float22bfloat162_rn(make_float2(C[j][0], C[j][1]));
            if (r1 < M)
                g_tb[(size_t)r1 * (HID / 2) + (col >> 1)] =
                    __float22bfloat162_rn(make_float2(C[j][2], C[j][3]));
        } else {
            float be0 = 0.f, be1 = 0.f;
            if (epi_bias) { be0 = epi_bias[col]; be1 = epi_bias[col + 1]; }
            if (r0 < M) {
                float2 v = make_float2(C[j][0] + be0, C[j][1] + be1);
                *(float2*)&outC[(size_t)r0 * 128 + col] = v;
            }
            if (r1 < M) {
                float2 v = make_float2(C[j][2] + be0, C[j][3] + be1);
                *(float2*)&outC[(size_t)r1 * 128 + col] = v;
            }
        }
    }
}

// ---------------- pull aggregation: warp = node, 2 edges in parallel -----
// Halves of the warp take even/odd pair-slots; each lane covers 8 features.
// Loops are WARP-UNIFORM: slot index idx = 2p + half <= 31 always; slots with
// idx >= m use padding (s=0, w=0) -> harmless load of row 0 scaled by 0.
__device__ __forceinline__ void unpack8(uint4 u, float* f) {
    float2 t0 = __bfloat1622float2(*(__nv_bfloat162*)&u.x);
    float2 t1 = __bfloat1622float2(*(__nv_bfloat162*)&u.y);
    float2 t2 = __bfloat1622float2(*(__nv_bfloat162*)&u.z);
    float2 t3 = __bfloat1622float2(*(__nv_bfloat162*)&u.w);
    f[0] = t0.x; f[1] = t0.y; f[2] = t1.x; f[3] = t1.y;
    f[4] = t2.x; f[5] = t2.y; f[6] = t3.x; f[7] = t3.y;
}

__global__ __launch_bounds__(256) void gather_kernel(int N) {
    const int n = (int)((blockIdx.x * blockDim.x + threadIdx.x) >> 5);
    if (n >= N) return;
    const int lane = threadIdx.x & 31;
    const int half = lane >> 4;       // 0 / 1: pair-slot parity
    const int fl = lane & 15;         // 16B feature chunk (8 bf16)
    const uint4* __restrict__ T4 = (const uint4*)g_tb;

    const int cnt = min(g_cursor[n], CAP);
    const float dn = rsqrtf((float)cnt + 1.0f);

    float acc[8];
    {   // self-loop added by half 0 only
        uint4 u = __ldg(&T4[(size_t)n * 16 + fl]);
        float f[8]; unpack8(u, f);
        const float s2 = half ? 0.0f : dn * dn;
#pragma unroll
        for (int k = 0; k < 8; k++) acc[k] = f[k] * s2;
    }

    const int base = n * CAP;
    for (int j0 = 0; j0 < cnt; j0 += 32) {
        const int m = min(32, cnt - j0);          // uniform across warp
        int   s_l = 0;                            // padding: row 0
        float w_l = 0.f;                          // padding: weight 0
        if (lane < m) {
            s_l = g_srcs[base + j0 + lane];
            w_l = g_w[base + j0 + lane];
        }
        const int npairs = (m + 1) >> 1;          // uniform
        int p = 0;
        for (; p + 4 <= npairs; p += 4) {         // uniform trip count
            int ia = 2 * p + half;                // <= 31 always
            int ib = ia + 2, ic = ia + 4, id = ia + 6;
            int   sa = __shfl_sync(0xFFFFFFFFu, s_l, ia);
            int   sb = __shfl_sync(0xFFFFFFFFu, s_l, ib);
            int   sc = __shfl_sync(0xFFFFFFFFu, s_l, ic);
            int   sd = __shfl_sync(0xFFFFFFFFu, s_l, id);
            float na = __shfl_sync(0xFFFFFFFFu, w_l, ia);
            float nb = __shfl_sync(0xFFFFFFFFu, w_l, ib);
            float nc = __shfl_sync(0xFFFFFFFFu, w_l, ic);
            float nd = __shfl_sync(0xFFFFFFFFu, w_l, id);
            uint4 ua = __ldg(&T4[(size_t)sa * 16 + fl]);
            uint4 ub = __ldg(&T4[(size_t)sb * 16 + fl]);
            uint4 uc = __ldg(&T4[(size_t)sc * 16 + fl]);
            uint4 ud = __ldg(&T4[(size_t)sd * 16 + fl]);
            float fa[8], fb[8], fc[8], fd[8];
            unpack8(ua, fa); unpack8(ub, fb); unpack8(uc, fc); unpack8(ud, fd);
#pragma unroll
            for (int k = 0; k < 8; k++) {
                acc[k] = fmaf(na, fa[k], acc[k]);
                acc[k] = fmaf(nb, fb[k], acc[k]);
                acc[k] = fmaf(nc, fc[k], acc[k]);
                acc[k] = fmaf(nd, fd[k], acc[k]);
            }
        }
        for (; p < npairs; p++) {                 // uniform trip count
            int ia = 2 * p + half;
            int   sa = __shfl_sync(0xFFFFFFFFu, s_l, ia);
            float na = __shfl_sync(0xFFFFFFFFu, w_l, ia);
            uint4 ua = __ldg(&T4[(size_t)sa * 16 + fl]);
            float fa[8]; unpack8(ua, fa);
#pragma unroll
            for (int k = 0; k < 8; k++) acc[k] = fmaf(na, fa[k], acc[k]);
        }
    }

    // combine the two halves (same feature chunk lives at lane^16)
#pragma unroll
    for (int k = 0; k < 8; k++)
        acc[k] += __shfl_xor_sync(0xFFFFFFFFu, acc[k], 16);

    // write: half 0 -> first float4 of chunk, half 1 -> second
    float4 o = half ? make_float4(acc[4], acc[5], acc[6], acc[7])
                    : make_float4(acc[0], acc[1], acc[2], acc[3]);
    ((float4*)(g_act + (size_t)n * HID))[fl * 2 + half] = o;
}

// ---------------- mean pool, 2-stage (batch sorted), fused bias+relu -----
__device__ __forceinline__ int lower_bound_batch(const void* batch, int n, int val, int is64) {
    int lo = 0, hi = n;
    while (lo < hi) {
        int mid = (lo + hi) >> 1;
        long long b = is64 ? ((const long long*)batch)[mid]
                           : (long long)((const int*)batch)[mid];
        if (b < val) lo = mid + 1; else hi = mid;
    }
    return lo;
}

__global__ void pool_partial_kernel(const void* __restrict__ batch,
                                    const float* __restrict__ bias, int n) {
    const int g = blockIdx.x;
    const int sub = blockIdx.y;
    const int tid = threadIdx.x;
    __shared__ int slo, shi;
    if (tid == 0) {
        int is64 = g_idx64;
        slo = lower_bound_batch(batch, n, g, is64);
        shi = lower_bound_batch(batch, n, g + 1, is64);
    }
    __syncthreads();
    const float b = bias[tid];
    const int lo = slo, hi = shi;
    float s0 = 0.f, s1 = 0.f;
    int r = lo + sub;
    for (; r + NSUB < hi; r += 2 * NSUB) {
        s0 += fmaxf(__ldg(&g_act[(size_t)r * HID + tid]) + b, 0.0f);
        s1 += fmaxf(__ldg(&g_act[(size_t)(r + NSUB) * HID + tid]) + b, 0.0f);
    }
    if (r < hi)
        s0 += fmaxf(__ldg(&g_act[(size_t)r * HID + tid]) + b, 0.0f);
    atomicAdd(&g_pooled[g * HID + tid], s0 + s1);
    if (sub == 0 && tid == 0) g_cnt[g] = (float)(hi - lo);
}

// ---------------- heads (divide pooled sum by count here) ----------------
__global__ void heads_kernel(
    const float* __restrict__ Wd, const float* __restrict__ bd,
    const float* __restrict__ Ws, const float* __restrict__ bsn,
    const float* __restrict__ Wr, const float* __restrict__ br,
    float* __restrict__ out)
{
    const int g = blockIdx.x;
    const int head = blockIdx.y;
    const int j = threadIdx.x;
    __shared__ float p[HID];
    const float inv = 1.0f / fmaxf(g_cnt[g], 1.0f);
    p[j] = g_pooled[g * HID + j] * inv;
    __syncthreads();

    const float* W = (head == 0) ? Wd : (head == 1) ? Ws : Wr;
    const float* b = (head == 0) ? bd : (head == 1) ? bsn : br;
    float s = b[j];
#pragma unroll 8
    for (int k = 0; k < HID; k++)
        s = fmaf(p[k], W[k * HID + j], s);
    out[(size_t)head * NGRAPH * HID + g * HID + j] = s;
}

// ---------------- launch --------------------------------------------------
extern "C" void kernel_launch(void* const* d_in, const int* in_sizes, int n_in,
                              void* d_out, int out_size)
{
    const float* x      = (const float*)d_in[0];
    const void*  eidx   = d_in[1];
    const void*  batch  = d_in[2];
    const float* W_in   = (const float*)d_in[3];
    const float* b_in   = (const float*)d_in[4];
    const float* conv_W = (const float*)d_in[5];
    const float* conv_b = (const float*)d_in[6];
    const float* W_def  = (const float*)d_in[7];
    const float* b_def  = (const float*)d_in[8];
    const float* W_syn  = (const float*)d_in[9];
    const float* b_syn  = (const float*)d_in[10];
    const float* W_rel  = (const float*)d_in[11];
    const float* b_rel  = (const float*)d_in[12];
    float* out = (float*)d_out;

    const int N = in_sizes[0] / HID;       // 50000
    const int E = in_sizes[1] / 2;         // 640000

    void *pa, *pz;
    cudaGetSymbolAddress(&pa, g_act);
    cudaGetSymbolAddress(&pz, g_zero_bias);
    float* act_buf = (float*)pa;
    const float* zero_b = (const float*)pz;

    static int smem_set = 0;
    if (!smem_set) {
        cudaFuncSetAttribute((const void*)gemm_kernel<false, false>,
                             cudaFuncAttributeMaxDynamicSharedMemorySize, SMEM_GEMM);
        cudaFuncSetAttribute((const void*)gemm_kernel<true, true>,
                             cudaFuncAttributeMaxDynamicSharedMemorySize, SMEM_GEMM);
        smem_set = 1;
    }

    const int T = 256;
    const int GB = (N + 127) / 128;
    const int GW = (N * 32 + T - 1) / T;   // warp-per-node grids

    // 0. index dtype detection + weight split/pack
    detect_dtype_kernel<<<1, 32>>>((const int*)eidx);
    pack_b_kernel<<<(5 * BFRAG_PER_W + T - 1) / T, T>>>(W_in, conv_W);

    // 1. adjacency build (+ zero pooled accumulators)
    zero_kernel<<<(N + T - 1) / T, T>>>(N);
    fill_kernel<<<(E + T - 1) / T, T>>>(eidx, E);
    edge_w_kernel<<<GW, T>>>(N);

    // 2. input layer: act = x @ W_in + b_in (fp32 pre-activation)
    gemm_kernel<false, false><<<GB, 512, SMEM_GEMM>>>(
        x, 0, nullptr, b_in, act_buf, N);

    // 3. GCN layers: GEMM (relu+bias fused, bf16 out) then pull-gather
    for (int l = 0; l < NLAYERS; l++) {
        const float* pro_b = (l == 0) ? zero_b : conv_b + (size_t)(l - 1) * HID;
        gemm_kernel<true, true><<<GB, 512, SMEM_GEMM>>>(
            act_buf, 1 + l, pro_b, nullptr, nullptr, N);
        gather_kernel<<<GW, T>>>(N);
    }

    // 4. global mean pool (2-stage, fused final bias+relu)
    pool_partial_kernel<<<dim3(NGRAPH, NSUB), HID>>>(
        batch, conv_b + (size_t)(NLAYERS - 1) * HID, N);

    // 5. output heads
    heads_kernel<<<dim3(NGRAPH, 3), HID>>>(W_def, b_def, W_syn, b_syn,
                                           W_rel, b_rel, out);
}

// round 12
// speedup vs baseline: 2.1958x; 1.3043x over previous
#include <cuda_runtime.h>
#include <cuda_bf16.h>
#include <cstdint>

#define NN      50000
#define NGRAPH  64
#define HID     128
#define NLAYERS 4
#define CAP     192     // per-node in-edge capacity (max expected in-degree ~45)
#define NSUB    16      // pool sub-slices per graph

// bf16 GEMM smem layout
#define BFRAG_PER_W (8 * 16 * 32)          // 4096 uint4 (8 k16-blocks)
#define SAB 66                              // A row stride in uint (bf16x2 pairs)
#define SMEM_GEMM (BFRAG_PER_W * 16 + 128 * SAB * 4)   // 65536 + 33792 = 99328

// ---------------- scratch (no allocations allowed) ----------------
__device__ __nv_bfloat162 g_tb[NN * (HID / 2)];  // bf16 messages (h @ W)
__device__ float    g_act[NN * HID];    // activation / aggregation buffer (fp32)
__device__ int      g_srcs[NN * CAP];   // bucketed in-edge source lists
__device__ float    g_w[NN * CAP];      // precomputed per-edge norm weights
__device__ int      g_cursor[NN];       // in-degree (w/o self loop)
__device__ uint4    g_Bfrag[5 * BFRAG_PER_W];  // fragment-packed bf16 hi/lo weights
__device__ float    g_pooled[NGRAPH * HID];
__device__ float    g_cnt[NGRAPH];
__device__ float    g_zero_bias[HID];   // stays all-zero
__device__ int      g_idx64;            // 1 if index buffers are int64

// ---------------- bf16 helpers -----------------------------------
__device__ __forceinline__ uint32_t pack_bf16x2(float lo_val, float hi_val) {
    __nv_bfloat162 h = __floats2bfloat162_rn(lo_val, hi_val);  // .x=lo .y=hi
    return *(uint32_t*)&h;
}
__device__ __forceinline__ void mma_bf16(
    float& c0, float& c1, float& c2, float& c3,
    uint32_t a0, uint32_t a1, uint32_t a2, uint32_t a3,
    uint32_t b0, uint32_t b1)
{
    asm volatile(
        "mma.sync.aligned.m16n8k16.row.col.f32.bf16.bf16.f32 "
        "{%0,%1,%2,%3}, {%4,%5,%6,%7}, {%8,%9}, {%0,%1,%2,%3};"
        : "+f"(c0), "+f"(c1), "+f"(c2), "+f"(c3)
        : "r"(a0), "r"(a1), "r"(a2), "r"(a3), "r"(b0), "r"(b1));
}

// ---------------- dtype detection (warp-parallel) ----------------
__global__ void detect_dtype_kernel(const int* __restrict__ e) {
    int lane = threadIdx.x;
    int nz = 0;
    if (e[1 + 2 * lane] != 0) nz = 1;
    if (e[1 + 2 * (lane + 32)] != 0) nz = 1;
    unsigned m = __ballot_sync(0xFFFFFFFFu, nz);
    if (lane == 0) g_idx64 = (m == 0u) ? 1 : 0;
}

// ---------------- one-time weight hi/lo split + fragment pack ------------
// For weight w, k16-block kb, n-block jn, lane (t=lane&3, g=lane>>2):
//   b0 covers k rows {kb*16+2t, +2t+1}, col jn*8+g; b1 covers rows {+2t+8, +2t+9}
// store uint4{bh0, bh1, bl0, bl1} (hi pair-regs then lo pair-regs).
__global__ void pack_b_kernel(const float* __restrict__ W_in,
                              const float* __restrict__ conv_W) {
    int i = blockIdx.x * blockDim.x + threadIdx.x;
    if (i >= 5 * BFRAG_PER_W) return;
    int lane = i & 31;
    int jn   = (i >> 5) & 15;
    int kb   = (i >> 9) & 7;
    int w    = i >> 12;
    int t = lane & 3, g = lane >> 2;
    const float* W = (w == 0) ? W_in : conv_W + (size_t)(w - 1) * HID * HID;
    const int n = jn * 8 + g;
    const int k0 = kb * 16;
    float w00 = W[(k0 + 2 * t) * HID + n];
    float w01 = W[(k0 + 2 * t + 1) * HID + n];
    float w10 = W[(k0 + 2 * t + 8) * HID + n];
    float w11 = W[(k0 + 2 * t + 9) * HID + n];
    float h00 = __bfloat162float(__float2bfloat16_rn(w00));
    float h01 = __bfloat162float(__float2bfloat16_rn(w01));
    float h10 = __bfloat162float(__float2bfloat16_rn(w10));
    float h11 = __bfloat162float(__float2bfloat16_rn(w11));
    uint32_t bh0 = pack_bf16x2(h00, h01);
    uint32_t bh1 = pack_bf16x2(h10, h11);
    uint32_t bl0 = pack_bf16x2(w00 - h00, w01 - h01);
    uint32_t bl1 = pack_bf16x2(w10 - h10, w11 - h11);
    g_Bfrag[i] = make_uint4(bh0, bh1, bl0, bl1);
}

// ---------------- adjacency build --------------------------------
__global__ void zero_kernel(int n) {
    int i = blockIdx.x * blockDim.x + threadIdx.x;
    if (i < n) g_cursor[i] = 0;
    if (i < NGRAPH * HID) g_pooled[i] = 0.0f;
}

__global__ void fill_kernel(const void* __restrict__ eidx, int E) {
    const int is64 = g_idx64;
    int i = blockIdx.x * blockDim.x + threadIdx.x;
    if (i < E) {
        int s, t;
        if (is64) {
            s = (int)((const long long*)eidx)[i];
            t = (int)((const long long*)eidx)[(long long)E + i];
        } else {
            s = ((const int*)eidx)[i];
            t = ((const int*)eidx)[E + i];
        }
        int p = atomicAdd(&g_cursor[t], 1);
        if (p < CAP) g_srcs[t * CAP + p] = s;
    }
}

// ---- per-edge weights, once: g_w[n*CAP+j] = dinv[src]*dinv[n] ----
__global__ __launch_bounds__(256) void edge_w_kernel(int N) {
    const int n = (int)((blockIdx.x * blockDim.x + threadIdx.x) >> 5);
    if (n >= N) return;
    const int lane = threadIdx.x & 31;
    const int cnt = min(g_cursor[n], CAP);
    const float dn = rsqrtf((float)cnt + 1.0f);
    for (int j = lane; j < cnt; j += 32) {
        int s = g_srcs[n * CAP + j];
        g_w[n * CAP + j] = rsqrtf((float)min(g_cursor[s], CAP) + 1.0f) * dn;
    }
}

// ---------------- bf16 tensor-core GEMM (A bf16, W hi+lo bf16) -----------
// C[M,128] = op(A)[M,128] @ W[128,128]
//   PRO:   op(a)[r][c] = relu(a[r][c] + pro_bias[c])
//   BFOUT: write bf16x2 to g_tb; else fp32 (+epi_bias) to outC
// 512 threads = 16 warps (8M x 2N), warp tile 16x64. 2 CTAs/SM.
template<bool PRO, bool BFOUT>
__global__ __launch_bounds__(512, 2) void gemm_kernel(
    const float* A, int widx,
    const float* __restrict__ pro_bias, const float* __restrict__ epi_bias,
    float* outC, int M)
{
    extern __shared__ uint4 smem_u4[];
    uint4* Bs = smem_u4;                              // [8][16][32] uint4
    uint32_t* As = (uint32_t*)(smem_u4 + BFRAG_PER_W);// [128][SAB] bf16x2

    const int tid = threadIdx.x;
    const int row0 = blockIdx.x * 128;

    // ---- load packed B frags (64KB) ----
    {
        const uint4* src = g_Bfrag + (size_t)widx * BFRAG_PER_W;
#pragma unroll
        for (int l = 0; l < BFRAG_PER_W / 512; l++)
            Bs[tid + l * 512] = src[tid + l * 512];
    }
    // ---- load A tile, optional fused bias+relu, convert to bf16 ----
#pragma unroll
    for (int l = 0; l < 8; l++) {
        int f = tid + l * 512;            // 0..4095 float4 slots
        int r = f >> 5;
        int c4 = f & 31;
        int grow = row0 + r;
        float4 v = make_float4(0.f, 0.f, 0.f, 0.f);
        if (grow < M) {
            v = *(const float4*)&A[(size_t)grow * 128 + c4 * 4];
            if (PRO) {
                float4 b = ((const float4*)pro_bias)[c4];
                v.x = fmaxf(v.x + b.x, 0.0f);
                v.y = fmaxf(v.y + b.y, 0.0f);
                v.z = fmaxf(v.z + b.z, 0.0f);
                v.w = fmaxf(v.w + b.w, 0.0f);
            }
        }
        As[r * SAB + c4 * 2]     = pack_bf16x2(v.x, v.y);
        As[r * SAB + c4 * 2 + 1] = pack_bf16x2(v.z, v.w);
    }
    __syncthreads();

    const int warp = tid >> 5;
    const int lane = tid & 31;
    const int g = lane >> 2;
    const int t = lane & 3;
    const int wm = (warp >> 1) * 16;
    const int jnb = (warp & 1) * 8;

    float C[8][4];
#pragma unroll
    for (int j = 0; j < 8; j++)
#pragma unroll
        for (int q = 0; q < 4; q++) C[j][q] = 0.0f;

#pragma unroll
    for (int kb = 0; kb < 8; kb++) {
        // A m16k16 fragment: pairs at (row, pair t) and (row, pair t+4)
        uint32_t a0 = As[(wm + g) * SAB + kb * 8 + t];
        uint32_t a1 = As[(wm + 8 + g) * SAB + kb * 8 + t];
        uint32_t a2 = As[(wm + g) * SAB + kb * 8 + t + 4];
        uint32_t a3 = As[(wm + 8 + g) * SAB + kb * 8 + t + 4];
#pragma unroll
        for (int j = 0; j < 8; j++) {
            uint4 bf = Bs[(kb * 16 + jnb + j) * 32 + lane];
            mma_bf16(C[j][0], C[j][1], C[j][2], C[j][3],
                     a0, a1, a2, a3, bf.x, bf.y);   // A x W_hi
            mma_bf16(C[j][0], C[j][1], C[j][2], C[j][3],
                     a0, a1, a2, a3, bf.z, bf.w);   // A x W_lo
        }
    }

    // ---- epilogue ----
#pragma unroll
    for (int j = 0; j < 8; j++) {
        const int col = (jnb + j) * 8 + 2 * t;
        const int r0 = row0 + wm + g;
        const int r1 = r0 + 8;
        if (BFOUT) {
            if (r0 < M)
                g_tb[(size_t)r0 * (HID / 2) + (col >> 1)] =
                    __float22bfloat162_rn(make_float2(C[j][0], C[j][1]));
            if (r1 < M)
                g_tb[(size_t)r1 * (HID / 2) + (col >> 1)] =
                    __float22bfloat162_rn(make_float2(C[j][2], C[j][3]));
        } else {
            float be0 = 0.f, be1 = 0.f;
            if (epi_bias) { be0 = epi_bias[col]; be1 = epi_bias[col + 1]; }
            if (r0 < M) {
                float2 v = make_float2(C[j][0] + be0, C[j][1] + be1);
                *(float2*)&outC[(size_t)r0 * 128 + col] = v;
            }
            if (r1 < M) {
                float2 v = make_float2(C[j][2] + be0, C[j][3] + be1);
                *(float2*)&outC[(size_t)r1 * 128 + col] = v;
            }
        }
    }
}

// ---------------- pull aggregation: warp = node, 2 edges in parallel -----
__device__ __forceinline__ void unpack8(uint4 u, float* f) {
    float2 t0 = __bfloat1622float2(*(__nv_bfloat162*)&u.x);
    float2 t1 = __bfloat1622float2(*(__nv_bfloat162*)&u.y);
    float2 t2 = __bfloat1622float2(*(__nv_bfloat162*)&u.z);
    float2 t3 = __bfloat1622float2(*(__nv_bfloat162*)&u.w);
    f[0] = t0.x; f[1] = t0.y; f[2] = t1.x; f[3] = t1.y;
    f[4] = t2.x; f[5] = t2.y; f[6] = t3.x; f[7] = t3.y;
}

__global__ __launch_bounds__(256) void gather_kernel(int N) {
    const int n = (int)((blockIdx.x * blockDim.x + threadIdx.x) >> 5);
    if (n >= N) return;
    const int lane = threadIdx.x & 31;
    const int half = lane >> 4;       // 0 / 1: pair-slot parity
    const int fl = lane & 15;         // 16B feature chunk (8 bf16)
    const uint4* __restrict__ T4 = (const uint4*)g_tb;

    const int cnt = min(g_cursor[n], CAP);
    const float dn = rsqrtf((float)cnt + 1.0f);

    float acc[8];
    {   // self-loop added by half 0 only
        uint4 u = __ldg(&T4[(size_t)n * 16 + fl]);
        float f[8]; unpack8(u, f);
        const float s2 = half ? 0.0f : dn * dn;
#pragma unroll
        for (int k = 0; k < 8; k++) acc[k] = f[k] * s2;
    }

    const int base = n * CAP;
    for (int j0 = 0; j0 < cnt; j0 += 32) {
        const int m = min(32, cnt - j0);          // uniform across warp
        int   s_l = 0;                            // padding: row 0
        float w_l = 0.f;                          // padding: weight 0
        if (lane < m) {
            s_l = g_srcs[base + j0 + lane];
            w_l = g_w[base + j0 + lane];
        }
        const int npairs = (m + 1) >> 1;          // uniform
        int p = 0;
        for (; p + 4 <= npairs; p += 4) {
            int ia = 2 * p + half;
            int ib = ia + 2, ic = ia + 4, id = ia + 6;
            int   sa = __shfl_sync(0xFFFFFFFFu, s_l, ia);
            int   sb = __shfl_sync(0xFFFFFFFFu, s_l, ib);
            int   sc = __shfl_sync(0xFFFFFFFFu, s_l, ic);
            int   sd = __shfl_sync(0xFFFFFFFFu, s_l, id);
            float na = __shfl_sync(0xFFFFFFFFu, w_l, ia);
            float nb = __shfl_sync(0xFFFFFFFFu, w_l, ib);
            float nc = __shfl_sync(0xFFFFFFFFu, w_l, ic);
            float nd = __shfl_sync(0xFFFFFFFFu, w_l, id);
            uint4 ua = __ldg(&T4[(size_t)sa * 16 + fl]);
            uint4 ub = __ldg(&T4[(size_t)sb * 16 + fl]);
            uint4 uc = __ldg(&T4[(size_t)sc * 16 + fl]);
            uint4 ud = __ldg(&T4[(size_t)sd * 16 + fl]);
            float fa[8], fb[8], fc[8], fd[8];
            unpack8(ua, fa); unpack8(ub, fb); unpack8(uc, fc); unpack8(ud, fd);
#pragma unroll
            for (int k = 0; k < 8; k++) {
                acc[k] = fmaf(na, fa[k], acc[k]);
                acc[k] = fmaf(nb, fb[k], acc[k]);
                acc[k] = fmaf(nc, fc[k], acc[k]);
                acc[k] = fmaf(nd, fd[k], acc[k]);
            }
        }
        for (; p < npairs; p++) {
            int ia = 2 * p + half;
            int   sa = __shfl_sync(0xFFFFFFFFu, s_l, ia);
            float na = __shfl_sync(0xFFFFFFFFu, w_l, ia);
            uint4 ua = __ldg(&T4[(size_t)sa * 16 + fl]);
            float fa[8]; unpack8(ua, fa);
#pragma unroll
            for (int k = 0; k < 8; k++) acc[k] = fmaf(na, fa[k], acc[k]);
        }
    }

#pragma unroll
    for (int k = 0; k < 8; k++)
        acc[k] += __shfl_xor_sync(0xFFFFFFFFu, acc[k], 16);

    float4 o = half ? make_float4(acc[4], acc[5], acc[6], acc[7])
                    : make_float4(acc[0], acc[1], acc[2], acc[3]);
    ((float4*)(g_act + (size_t)n * HID))[fl * 2 + half] = o;
}

// ---------------- mean pool, 2-stage (batch sorted), fused bias+relu -----
__device__ __forceinline__ int lower_bound_batch(const void* batch, int n, int val, int is64) {
    int lo = 0, hi = n;
    while (lo < hi) {
        int mid = (lo + hi) >> 1;
        long long b = is64 ? ((const long long*)batch)[mid]
                           : (long long)((const int*)batch)[mid];
        if (b < val) lo = mid + 1; else hi = mid;
    }
    return lo;
}

__global__ void pool_partial_kernel(const void* __restrict__ batch,
                                    const float* __restrict__ bias, int n) {
    const int g = blockIdx.x;
    const int sub = blockIdx.y;
    const int tid = threadIdx.x;
    __shared__ int slo, shi;
    if (tid == 0) {
        int is64 = g_idx64;
        slo = lower_bound_batch(batch, n, g, is64);
        shi = lower_bound_batch(batch, n, g + 1, is64);
    }
    __syncthreads();
    const float b = bias[tid];
    const int lo = slo, hi = shi;
    float s0 = 0.f, s1 = 0.f;
    int r = lo + sub;
    for (; r + NSUB < hi; r += 2 * NSUB) {
        s0 += fmaxf(__ldg(&g_act[(size_t)r * HID + tid]) + b, 0.0f);
        s1 += fmaxf(__ldg(&g_act[(size_t)(r + NSUB) * HID + tid]) + b, 0.0f);
    }
    if (r < hi)
        s0 += fmaxf(__ldg(&g_act[(size_t)r * HID + tid]) + b, 0.0f);
    atomicAdd(&g_pooled[g * HID + tid], s0 + s1);
    if (sub == 0 && tid == 0) g_cnt[g] = (float)(hi - lo);
}

// ---------------- heads (divide pooled sum by count here) ----------------
__global__ void heads_kernel(
    const float* __restrict__ Wd, const float* __restrict__ bd,
    const float* __restrict__ Ws, const float* __restrict__ bsn,
    const float* __restrict__ Wr, const float* __restrict__ br,
    float* __restrict__ out)
{
    const int g = blockIdx.x;
    const int head = blockIdx.y;
    const int j = threadIdx.x;
    __shared__ float p[HID];
    const float inv = 1.0f / fmaxf(g_cnt[g], 1.0f);
    p[j] = g_pooled[g * HID + j] * inv;
    __syncthreads();

    const float* W = (head == 0) ? Wd : (head == 1) ? Ws : Wr;
    const float* b = (head == 0) ? bd : (head == 1) ? bsn : br;
    float s = b[j];
#pragma unroll 8
    for (int k = 0; k < HID; k++)
        s = fmaf(p[k], W[k * HID + j], s);
    out[(size_t)head * NGRAPH * HID + g * HID + j] = s;
}

// ---------------- launch --------------------------------------------------
extern "C" void kernel_launch(void* const* d_in, const int* in_sizes, int n_in,
                              void* d_out, int out_size)
{
    const float* x      = (const float*)d_in[0];
    const void*  eidx   = d_in[1];
    const void*  batch  = d_in[2];
    const float* W_in   = (const float*)d_in[3];
    const float* b_in   = (const float*)d_in[4];
    const float* conv_W = (const float*)d_in[5];
    const float* conv_b = (const float*)d_in[6];
    const float* W_def  = (const float*)d_in[7];
    const float* b_def  = (const float*)d_in[8];
    const float* W_syn  = (const float*)d_in[9];
    const float* b_syn  = (const float*)d_in[10];
    const float* W_rel  = (const float*)d_in[11];
    const float* b_rel  = (const float*)d_in[12];
    float* out = (float*)d_out;

    const int N = in_sizes[0] / HID;       // 50000
    const int E = in_sizes[1] / 2;         // 640000

    void *pa, *pz;
    cudaGetSymbolAddress(&pa, g_act);
    cudaGetSymbolAddress(&pz, g_zero_bias);
    float* act_buf = (float*)pa;
    const float* zero_b = (const float*)pz;

    static int smem_set = 0;
    if (!smem_set) {
        cudaFuncSetAttribute((const void*)gemm_kernel<false, false>,
                             cudaFuncAttributeMaxDynamicSharedMemorySize, SMEM_GEMM);
        cudaFuncSetAttribute((const void*)gemm_kernel<true, true>,
                             cudaFuncAttributeMaxDynamicSharedMemorySize, SMEM_GEMM);
        smem_set = 1;
    }

    const int T = 256;
    const int GB = (N + 127) / 128;
    const int GW = (N * 32 + T - 1) / T;   // warp-per-node grids

    // 0. index dtype detection + weight split/pack
    detect_dtype_kernel<<<1, 32>>>((const int*)eidx);
    pack_b_kernel<<<(5 * BFRAG_PER_W + T - 1) / T, T>>>(W_in, conv_W);

    // 1. adjacency build (+ zero pooled accumulators)
    zero_kernel<<<(N + T - 1) / T, T>>>(N);
    fill_kernel<<<(E + T - 1) / T, T>>>(eidx, E);
    edge_w_kernel<<<GW, T>>>(N);

    // 2. input layer: act = x @ W_in + b_in (fp32 pre-activation)
    gemm_kernel<false, false><<<GB, 512, SMEM_GEMM>>>(
        x, 0, nullptr, b_in, act_buf, N);

    // 3. GCN layers: GEMM (relu+bias fused, bf16 out) then pull-gather
    for (int l = 0; l < NLAYERS; l++) {
        const float* pro_b = (l == 0) ? zero_b : conv_b + (size_t)(l - 1) * HID;
        gemm_kernel<true, true><<<GB, 512, SMEM_GEMM>>>(
            act_buf, 1 + l, pro_b, nullptr, nullptr, N);
        gather_kernel<<<GW, T>>>(N);
    }

    // 4. global mean pool (2-stage, fused final bias+relu)
    pool_partial_kernel<<<dim3(NGRAPH, NSUB), HID>>>(
        batch, conv_b + (size_t)(NLAYERS - 1) * HID, N);

    // 5. output heads
    heads_kernel<<<dim3(NGRAPH, 3), HID>>>(W_def, b_def, W_syn, b_syn,
                                           W_rel, b_rel, out);
}

// round 13
// speedup vs baseline: 2.2289x; 1.0151x over previous
#include <cuda_runtime.h>
#include <cuda_bf16.h>
#include <cstdint>

#define NN      50000
#define NGRAPH  64
#define HID     128
#define NLAYERS 4
#define CAP     192     // per-node in-edge capacity (max expected in-degree ~45)
#define NSUB    16      // pool sub-slices per graph

// bf16 GEMM smem layout
#define BFRAG_PER_W (8 * 16 * 32)          // 4096 uint4 (8 k16-blocks)
#define SAB 66                              // A row stride in uint (bf16x2 pairs)
#define SMEM_GEMM (BFRAG_PER_W * 16 + 128 * SAB * 4)   // 65536 + 33792 = 99328

// setup kernel grid partition
#define PACK_BLKS  ((5 * BFRAG_PER_W + 255) / 256)     // 80
#define ZERO_BLKS  ((NN + 255) / 256)                  // 196
#define SETUP_BLKS (PACK_BLKS + ZERO_BLKS + 1)

// ---------------- scratch (no allocations allowed) ----------------
__device__ __nv_bfloat162 g_tb[NN * (HID / 2)];  // bf16 messages (h @ W)
__device__ float    g_act[NN * HID];    // activation / aggregation buffer (fp32)
__device__ int      g_srcs[NN * CAP];   // bucketed in-edge source lists
__device__ float    g_w[NN * CAP];      // precomputed per-edge norm weights
__device__ int      g_cursor[NN];       // in-degree (w/o self loop)
__device__ uint4    g_Bfrag[5 * BFRAG_PER_W];  // fragment-packed bf16 hi/lo weights
__device__ float    g_pooled[NGRAPH * HID];
__device__ float    g_cnt[NGRAPH];
__device__ float    g_zero_bias[HID];   // stays all-zero
__device__ int      g_idx64;            // 1 if index buffers are int64

// ---------------- bf16 helpers -----------------------------------
__device__ __forceinline__ uint32_t pack_bf16x2(float lo_val, float hi_val) {
    __nv_bfloat162 h = __floats2bfloat162_rn(lo_val, hi_val);  // .x=lo .y=hi
    return *(uint32_t*)&h;
}
__device__ __forceinline__ void mma_bf16(
    float& c0, float& c1, float& c2, float& c3,
    uint32_t a0, uint32_t a1, uint32_t a2, uint32_t a3,
    uint32_t b0, uint32_t b1)
{
    asm volatile(
        "mma.sync.aligned.m16n8k16.row.col.f32.bf16.bf16.f32 "
        "{%0,%1,%2,%3}, {%4,%5,%6,%7}, {%8,%9}, {%0,%1,%2,%3};"
        : "+f"(c0), "+f"(c1), "+f"(c2), "+f"(c3)
        : "r"(a0), "r"(a1), "r"(a2), "r"(a3), "r"(b0), "r"(b1));
}

// ---------------- fused setup: pack B + zero cursors/pooled + detect -----
__global__ void setup_kernel(const float* __restrict__ W_in,
                             const float* __restrict__ conv_W,
                             const int* __restrict__ e) {
    const int bid = blockIdx.x;
    const int tid = threadIdx.x;
    if (bid < PACK_BLKS) {
        int i = bid * 256 + tid;
        if (i >= 5 * BFRAG_PER_W) return;
        int lane = i & 31;
        int jn   = (i >> 5) & 15;
        int kb   = (i >> 9) & 7;
        int w    = i >> 12;
        int t = lane & 3, g = lane >> 2;
        const float* W = (w == 0) ? W_in : conv_W + (size_t)(w - 1) * HID * HID;
        const int n = jn * 8 + g;
        const int k0 = kb * 16;
        float w00 = W[(k0 + 2 * t) * HID + n];
        float w01 = W[(k0 + 2 * t + 1) * HID + n];
        float w10 = W[(k0 + 2 * t + 8) * HID + n];
        float w11 = W[(k0 + 2 * t + 9) * HID + n];
        float h00 = __bfloat162float(__float2bfloat16_rn(w00));
        float h01 = __bfloat162float(__float2bfloat16_rn(w01));
        float h10 = __bfloat162float(__float2bfloat16_rn(w10));
        float h11 = __bfloat162float(__float2bfloat16_rn(w11));
        g_Bfrag[i] = make_uint4(pack_bf16x2(h00, h01), pack_bf16x2(h10, h11),
                                pack_bf16x2(w00 - h00, w01 - h01),
                                pack_bf16x2(w10 - h10, w11 - h11));
    } else if (bid < PACK_BLKS + ZERO_BLKS) {
        int i = (bid - PACK_BLKS) * 256 + tid;
        if (i < NN) g_cursor[i] = 0;
        if (i < NGRAPH * HID) g_pooled[i] = 0.0f;
    } else {
        // dtype detection (warp 0 of last block)
        if (tid < 32) {
            int nz = 0;
            if (e[1 + 2 * tid] != 0) nz = 1;
            if (e[1 + 2 * (tid + 32)] != 0) nz = 1;
            unsigned m = __ballot_sync(0xFFFFFFFFu, nz);
            if (tid == 0) g_idx64 = (m == 0u) ? 1 : 0;
        }
    }
}

// ---------------- adjacency build --------------------------------
__global__ void fill_kernel(const void* __restrict__ eidx, int E) {
    const int is64 = g_idx64;
    int i = blockIdx.x * blockDim.x + threadIdx.x;
    if (i < E) {
        int s, t;
        if (is64) {
            s = (int)((const long long*)eidx)[i];
            t = (int)((const long long*)eidx)[(long long)E + i];
        } else {
            s = ((const int*)eidx)[i];
            t = ((const int*)eidx)[E + i];
        }
        int p = atomicAdd(&g_cursor[t], 1);
        if (p < CAP) g_srcs[t * CAP + p] = s;
    }
}

// ---- per-edge weights, once: g_w[n*CAP+j] = dinv[src]*dinv[n] ----
__global__ __launch_bounds__(256) void edge_w_kernel(int N) {
    const int n = (int)((blockIdx.x * blockDim.x + threadIdx.x) >> 5);
    if (n >= N) return;
    const int lane = threadIdx.x & 31;
    const int cnt = min(g_cursor[n], CAP);
    const float dn = rsqrtf((float)cnt + 1.0f);
    for (int j = lane; j < cnt; j += 32) {
        int s = g_srcs[n * CAP + j];
        g_w[n * CAP + j] = rsqrtf((float)min(g_cursor[s], CAP) + 1.0f) * dn;
    }
}

// ---------------- bf16 tensor-core GEMM (A bf16, W hi+lo bf16) -----------
// C[M,128] = op(A)[M,128] @ W[128,128]
//   PRO:   op(a)[r][c] = relu(a[r][c] + pro_bias[c])
//   BFOUT: write bf16x2 to g_tb; else fp32 (+epi_bias) to outC
// 512 threads = 16 warps (8M x 2N), warp tile 16x64. 2 CTAs/SM.
template<bool PRO, bool BFOUT>
__global__ __launch_bounds__(512, 2) void gemm_kernel(
    const float* A, int widx,
    const float* __restrict__ pro_bias, const float* __restrict__ epi_bias,
    float* outC, int M)
{
    extern __shared__ uint4 smem_u4[];
    uint4* Bs = smem_u4;                              // [8][16][32] uint4
    uint32_t* As = (uint32_t*)(smem_u4 + BFRAG_PER_W);// [128][SAB] bf16x2

    const int tid = threadIdx.x;
    const int row0 = blockIdx.x * 128;

    // ---- load packed B frags (64KB) ----
    {
        const uint4* src = g_Bfrag + (size_t)widx * BFRAG_PER_W;
#pragma unroll
        for (int l = 0; l < BFRAG_PER_W / 512; l++)
            Bs[tid + l * 512] = src[tid + l * 512];
    }
    // ---- load A tile, optional fused bias+relu, convert to bf16 ----
#pragma unroll
    for (int l = 0; l < 8; l++) {
        int f = tid + l * 512;            // 0..4095 float4 slots
        int r = f >> 5;
        int c4 = f & 31;
        int grow = row0 + r;
        float4 v = make_float4(0.f, 0.f, 0.f, 0.f);
        if (grow < M) {
            v = *(const float4*)&A[(size_t)grow * 128 + c4 * 4];
            if (PRO) {
                float4 b = ((const float4*)pro_bias)[c4];
                v.x = fmaxf(v.x + b.x, 0.0f);
                v.y = fmaxf(v.y + b.y, 0.0f);
                v.z = fmaxf(v.z + b.z, 0.0f);
                v.w = fmaxf(v.w + b.w, 0.0f);
            }
        }
        As[r * SAB + c4 * 2]     = pack_bf16x2(v.x, v.y);
        As[r * SAB + c4 * 2 + 1] = pack_bf16x2(v.z, v.w);
    }
    __syncthreads();

    const int warp = tid >> 5;
    const int lane = tid & 31;
    const int g = lane >> 2;
    const int t = lane & 3;
    const int wm = (warp >> 1) * 16;
    const int jnb = (warp & 1) * 8;

    float C[8][4];
#pragma unroll
    for (int j = 0; j < 8; j++)
#pragma unroll
        for (int q = 0; q < 4; q++) C[j][q] = 0.0f;

#pragma unroll
    for (int kb = 0; kb < 8; kb++) {
        uint32_t a0 = As[(wm + g) * SAB + kb * 8 + t];
        uint32_t a1 = As[(wm + 8 + g) * SAB + kb * 8 + t];
        uint32_t a2 = As[(wm + g) * SAB + kb * 8 + t + 4];
        uint32_t a3 = As[(wm + 8 + g) * SAB + kb * 8 + t + 4];
#pragma unroll
        for (int j = 0; j < 8; j++) {
            uint4 bf = Bs[(kb * 16 + jnb + j) * 32 + lane];
            mma_bf16(C[j][0], C[j][1], C[j][2], C[j][3],
                     a0, a1, a2, a3, bf.x, bf.y);   // A x W_hi
            mma_bf16(C[j][0], C[j][1], C[j][2], C[j][3],
                     a0, a1, a2, a3, bf.z, bf.w);   // A x W_lo
        }
    }

    // ---- epilogue ----
#pragma unroll
    for (int j = 0; j < 8; j++) {
        const int col = (jnb + j) * 8 + 2 * t;
        const int r0 = row0 + wm + g;
        const int r1 = r0 + 8;
        if (BFOUT) {
            if (r0 < M)
                g_tb[(size_t)r0 * (HID / 2) + (col >> 1)] =
                    __float22bfloat162_rn(make_float2(C[j][0], C[j][1]));
            if (r1 < M)
                g_tb[(size_t)r1 * (HID / 2) + (col >> 1)] =
                    __float22bfloat162_rn(make_float2(C[j][2], C[j][3]));
        } else {
            float be0 = 0.f, be1 = 0.f;
            if (epi_bias) { be0 = epi_bias[col]; be1 = epi_bias[col + 1]; }
            if (r0 < M) {
                float2 v = make_float2(C[j][0] + be0, C[j][1] + be1);
                *(float2*)&outC[(size_t)r0 * 128 + col] = v;
            }
            if (r1 < M) {
                float2 v = make_float2(C[j][2] + be0, C[j][3] + be1);
                *(float2*)&outC[(size_t)r1 * 128 + col] = v;
            }
        }
    }
}

// ---------------- pull aggregation: warp = node, 2 edges in parallel -----
// Pair-slot loop rounded up to ILP-4: padded slots have s=0,w=0 (harmless
// hot-line load x 0). All control flow warp-uniform; all shfl full-mask.
__device__ __forceinline__ void unpack8(uint4 u, float* f) {
    float2 t0 = __bfloat1622float2(*(__nv_bfloat162*)&u.x);
    float2 t1 = __bfloat1622float2(*(__nv_bfloat162*)&u.y);
    float2 t2 = __bfloat1622float2(*(__nv_bfloat162*)&u.z);
    float2 t3 = __bfloat1622float2(*(__nv_bfloat162*)&u.w);
    f[0] = t0.x; f[1] = t0.y; f[2] = t1.x; f[3] = t1.y;
    f[4] = t2.x; f[5] = t2.y; f[6] = t3.x; f[7] = t3.y;
}

__global__ __launch_bounds__(256) void gather_kernel(int N) {
    const int n = (int)((blockIdx.x * blockDim.x + threadIdx.x) >> 5);
    if (n >= N) return;
    const int lane = threadIdx.x & 31;
    const int half = lane >> 4;       // 0 / 1: pair-slot parity
    const int fl = lane & 15;         // 16B feature chunk (8 bf16)
    const uint4* __restrict__ T4 = (const uint4*)g_tb;

    const int cnt = min(g_cursor[n], CAP);
    const float dn = rsqrtf((float)cnt + 1.0f);

    float acc[8];
    {   // self-loop added by half 0 only
        uint4 u = __ldg(&T4[(size_t)n * 16 + fl]);
        float f[8]; unpack8(u, f);
        const float s2 = half ? 0.0f : dn * dn;
#pragma unroll
        for (int k = 0; k < 8; k++) acc[k] = f[k] * s2;
    }

    const int base = n * CAP;
    for (int j0 = 0; j0 < cnt; j0 += 32) {
        const int m = min(32, cnt - j0);          // uniform across warp
        int   s_l = 0;                            // padding: row 0
        float w_l = 0.f;                          // padding: weight 0
        if (lane < m) {
            s_l = g_srcs[base + j0 + lane];
            w_l = g_w[base + j0 + lane];
        }
        // pairs rounded up to multiple of 4 -> single ILP-4 loop, no remainder
        const int npairs4 = ((((m + 1) >> 1) + 3) & ~3);   // <= 16
        for (int p = 0; p < npairs4; p += 4) {
            int ia = 2 * p + half;                // max 2*12+1+6 = 31
            int ib = ia + 2, ic = ia + 4, id = ia + 6;
            int   sa = __shfl_sync(0xFFFFFFFFu, s_l, ia);
            int   sb = __shfl_sync(0xFFFFFFFFu, s_l, ib);
            int   sc = __shfl_sync(0xFFFFFFFFu, s_l, ic);
            int   sd = __shfl_sync(0xFFFFFFFFu, s_l, id);
            float na = __shfl_sync(0xFFFFFFFFu, w_l, ia);
            float nb = __shfl_sync(0xFFFFFFFFu, w_l, ib);
            float nc = __shfl_sync(0xFFFFFFFFu, w_l, ic);
            float nd = __shfl_sync(0xFFFFFFFFu, w_l, id);
            uint4 ua = __ldg(&T4[(size_t)sa * 16 + fl]);
            uint4 ub = __ldg(&T4[(size_t)sb * 16 + fl]);
            uint4 uc = __ldg(&T4[(size_t)sc * 16 + fl]);
            uint4 ud = __ldg(&T4[(size_t)sd * 16 + fl]);
            float fa[8], fb[8], fc[8], fd[8];
            unpack8(ua, fa); unpack8(ub, fb); unpack8(uc, fc); unpack8(ud, fd);
#pragma unroll
            for (int k = 0; k < 8; k++) {
                acc[k] = fmaf(na, fa[k], acc[k]);
                acc[k] = fmaf(nb, fb[k], acc[k]);
                acc[k] = fmaf(nc, fc[k], acc[k]);
                acc[k] = fmaf(nd, fd[k], acc[k]);
            }
        }
    }

#pragma unroll
    for (int k = 0; k < 8; k++)
        acc[k] += __shfl_xor_sync(0xFFFFFFFFu, acc[k], 16);

    float4 o = half ? make_float4(acc[4], acc[5], acc[6], acc[7])
                    : make_float4(acc[0], acc[1], acc[2], acc[3]);
    ((float4*)(g_act + (size_t)n * HID))[fl * 2 + half] = o;
}

// ---------------- mean pool, 2-stage (batch sorted), fused bias+relu -----
__device__ __forceinline__ int lower_bound_batch(const void* batch, int n, int val, int is64) {
    int lo = 0, hi = n;
    while (lo < hi) {
        int mid = (lo + hi) >> 1;
        long long b = is64 ? ((const long long*)batch)[mid]
                           : (long long)((const int*)batch)[mid];
        if (b < val) lo = mid + 1; else hi = mid;
    }
    return lo;
}

__global__ void pool_partial_kernel(const void* __restrict__ batch,
                                    const float* __restrict__ bias, int n) {
    const int g = blockIdx.x;
    const int sub = blockIdx.y;
    const int tid = threadIdx.x;
    __shared__ int slo, shi;
    if (tid == 0) {
        int is64 = g_idx64;
        slo = lower_bound_batch(batch, n, g, is64);
        shi = lower_bound_batch(batch, n, g + 1, is64);
    }
    __syncthreads();
    const float b = bias[tid];
    const int lo = slo, hi = shi;
    float s0 = 0.f, s1 = 0.f;
    int r = lo + sub;
    for (; r + NSUB < hi; r += 2 * NSUB) {
        s0 += fmaxf(__ldg(&g_act[(size_t)r * HID + tid]) + b, 0.0f);
        s1 += fmaxf(__ldg(&g_act[(size_t)(r + NSUB) * HID + tid]) + b, 0.0f);
    }
    if (r < hi)
        s0 += fmaxf(__ldg(&g_act[(size_t)r * HID + tid]) + b, 0.0f);
    atomicAdd(&g_pooled[g * HID + tid], s0 + s1);
    if (sub == 0 && tid == 0) g_cnt[g] = (float)(hi - lo);
}

// ---------------- heads (divide pooled sum by count here) ----------------
__global__ void heads_kernel(
    const float* __restrict__ Wd, const float* __restrict__ bd,
    const float* __restrict__ Ws, const float* __restrict__ bsn,
    const float* __restrict__ Wr, const float* __restrict__ br,
    float* __restrict__ out)
{
    const int g = blockIdx.x;
    const int head = blockIdx.y;
    const int j = threadIdx.x;
    __shared__ float p[HID];
    const float inv = 1.0f / fmaxf(g_cnt[g], 1.0f);
    p[j] = g_pooled[g * HID + j] * inv;
    __syncthreads();

    const float* W = (head == 0) ? Wd : (head == 1) ? Ws : Wr;
    const float* b = (head == 0) ? bd : (head == 1) ? bsn : br;
    float s = b[j];
#pragma unroll 8
    for (int k = 0; k < HID; k++)
        s = fmaf(p[k], W[k * HID + j], s);
    out[(size_t)head * NGRAPH * HID + g * HID + j] = s;
}

// ---------------- launch --------------------------------------------------
extern "C" void kernel_launch(void* const* d_in, const int* in_sizes, int n_in,
                              void* d_out, int out_size)
{
    const float* x      = (const float*)d_in[0];
    const void*  eidx   = d_in[1];
    const void*  batch  = d_in[2];
    const float* W_in   = (const float*)d_in[3];
    const float* b_in   = (const float*)d_in[4];
    const float* conv_W = (const float*)d_in[5];
    const float* conv_b = (const float*)d_in[6];
    const float* W_def  = (const float*)d_in[7];
    const float* b_def  = (const float*)d_in[8];
    const float* W_syn  = (const float*)d_in[9];
    const float* b_syn  = (const float*)d_in[10];
    const float* W_rel  = (const float*)d_in[11];
    const float* b_rel  = (const float*)d_in[12];
    float* out = (float*)d_out;

    const int N = in_sizes[0] / HID;       // 50000
    const int E = in_sizes[1] / 2;         // 640000

    void *pa, *pz;
    cudaGetSymbolAddress(&pa, g_act);
    cudaGetSymbolAddress(&pz, g_zero_bias);
    float* act_buf = (float*)pa;
    const float* zero_b = (const float*)pz;

    static int smem_set = 0;
    if (!smem_set) {
        cudaFuncSetAttribute((const void*)gemm_kernel<false, false>,
                             cudaFuncAttributeMaxDynamicSharedMemorySize, SMEM_GEMM);
        cudaFuncSetAttribute((const void*)gemm_kernel<true, true>,
                             cudaFuncAttributeMaxDynamicSharedMemorySize, SMEM_GEMM);
        smem_set = 1;
    }

    const int T = 256;
    const int GB = (N + 127) / 128;
    const int GW = (N * 32 + T - 1) / T;   // warp-per-node grids

    // 0. fused setup: pack weights + zero cursors/pooled + dtype detect
    setup_kernel<<<SETUP_BLKS, T>>>(W_in, conv_W, (const int*)eidx);

    // 1. adjacency build
    fill_kernel<<<(E + T - 1) / T, T>>>(eidx, E);
    edge_w_kernel<<<GW, T>>>(N);

    // 2. input layer: act = x @ W_in + b_in (fp32 pre-activation)
    gemm_kernel<false, false><<<GB, 512, SMEM_GEMM>>>(
        x, 0, nullptr, b_in, act_buf, N);

    // 3. GCN layers: GEMM (relu+bias fused, bf16 out) then pull-gather
    for (int l = 0; l < NLAYERS; l++) {
        const float* pro_b = (l == 0) ? zero_b : conv_b + (size_t)(l - 1) * HID;
        gemm_kernel<true, true><<<GB, 512, SMEM_GEMM>>>(
            act_buf, 1 + l, pro_b, nullptr, nullptr, N);
        gather_kernel<<<GW, T>>>(N);
    }

    // 4. global mean pool (2-stage, fused final bias+relu)
    pool_partial_kernel<<<dim3(NGRAPH, NSUB), HID>>>(
        batch, conv_b + (size_t)(NLAYERS - 1) * HID, N);

    // 5. output heads
    heads_kernel<<<dim3(NGRAPH, 3), HID>>>(W_def, b_def, W_syn, b_syn,
                                           W_rel, b_rel, out);
}

// round 14
// speedup vs baseline: 2.3127x; 1.0376x over previous
#include <cuda_runtime.h>
#include <cuda_bf16.h>
#include <cstdint>

#define NN      50000
#define NGRAPH  64
#define HID     128
#define NLAYERS 4
#define CAP     192     // per-node in-edge capacity (max expected in-degree ~45)
#define NSUB    16      // pool sub-slices per graph

// bf16 GEMM smem layout
#define BFRAG_PER_W (8 * 16 * 32)          // 4096 uint4 (8 k16-blocks)
#define SAB 68                              // A row stride in uint: banks 4g+t, conflict-free
#define SMEM_GEMM (BFRAG_PER_W * 16 + 128 * SAB * 4)   // 65536 + 34816 = 100352

// setup kernel grid partition
#define PACK_BLKS  ((5 * BFRAG_PER_W + 255) / 256)     // 80
#define ZERO_BLKS  ((NN + 255) / 256)                  // 196
#define SETUP_BLKS (PACK_BLKS + ZERO_BLKS + 1)

// ---------------- scratch (no allocations allowed) ----------------
__device__ __nv_bfloat162 g_tb[NN * (HID / 2)];  // bf16 messages (h @ W)
__device__ __nv_bfloat162 g_ab[NN * (HID / 2)];  // bf16 activations (pre-act)
__device__ int      g_srcs[NN * CAP];   // bucketed in-edge source lists
__device__ float    g_w[NN * CAP];      // precomputed per-edge norm weights
__device__ int      g_cursor[NN];       // in-degree (w/o self loop)
__device__ uint4    g_Bfrag[5 * BFRAG_PER_W];  // fragment-packed bf16 hi/lo weights
__device__ float    g_pooled[NGRAPH * HID];
__device__ float    g_cnt[NGRAPH];
__device__ float    g_zero_bias[HID];   // stays all-zero
__device__ int      g_idx64;            // 1 if index buffers are int64

// ---------------- bf16 helpers -----------------------------------
__device__ __forceinline__ uint32_t pack_bf16x2(float lo_val, float hi_val) {
    __nv_bfloat162 h = __floats2bfloat162_rn(lo_val, hi_val);  // .x=lo .y=hi
    return *(uint32_t*)&h;
}
__device__ __forceinline__ float2 unpack_bf16x2(uint32_t u) {
    return __bfloat1622float2(*(__nv_bfloat162*)&u);
}
__device__ __forceinline__ void mma_bf16(
    float& c0, float& c1, float& c2, float& c3,
    uint32_t a0, uint32_t a1, uint32_t a2, uint32_t a3,
    uint32_t b0, uint32_t b1)
{
    asm volatile(
        "mma.sync.aligned.m16n8k16.row.col.f32.bf16.bf16.f32 "
        "{%0,%1,%2,%3}, {%4,%5,%6,%7}, {%8,%9}, {%0,%1,%2,%3};"
        : "+f"(c0), "+f"(c1), "+f"(c2), "+f"(c3)
        : "r"(a0), "r"(a1), "r"(a2), "r"(a3), "r"(b0), "r"(b1));
}

// ---------------- fused setup: pack B + zero cursors/pooled + detect -----
__global__ void setup_kernel(const float* __restrict__ W_in,
                             const float* __restrict__ conv_W,
                             const int* __restrict__ e) {
    const int bid = blockIdx.x;
    const int tid = threadIdx.x;
    if (bid < PACK_BLKS) {
        int i = bid * 256 + tid;
        if (i >= 5 * BFRAG_PER_W) return;
        int lane = i & 31;
        int jn   = (i >> 5) & 15;
        int kb   = (i >> 9) & 7;
        int w    = i >> 12;
        int t = lane & 3, g = lane >> 2;
        const float* W = (w == 0) ? W_in : conv_W + (size_t)(w - 1) * HID * HID;
        const int n = jn * 8 + g;
        const int k0 = kb * 16;
        float w00 = W[(k0 + 2 * t) * HID + n];
        float w01 = W[(k0 + 2 * t + 1) * HID + n];
        float w10 = W[(k0 + 2 * t + 8) * HID + n];
        float w11 = W[(k0 + 2 * t + 9) * HID + n];
        float h00 = __bfloat162float(__float2bfloat16_rn(w00));
        float h01 = __bfloat162float(__float2bfloat16_rn(w01));
        float h10 = __bfloat162float(__float2bfloat16_rn(w10));
        float h11 = __bfloat162float(__float2bfloat16_rn(w11));
        g_Bfrag[i] = make_uint4(pack_bf16x2(h00, h01), pack_bf16x2(h10, h11),
                                pack_bf16x2(w00 - h00, w01 - h01),
                                pack_bf16x2(w10 - h10, w11 - h11));
    } else if (bid < PACK_BLKS + ZERO_BLKS) {
        int i = (bid - PACK_BLKS) * 256 + tid;
        if (i < NN) g_cursor[i] = 0;
        if (i < NGRAPH * HID) g_pooled[i] = 0.0f;
    } else {
        if (tid < 32) {
            int nz = 0;
            if (e[1 + 2 * tid] != 0) nz = 1;
            if (e[1 + 2 * (tid + 32)] != 0) nz = 1;
            unsigned m = __ballot_sync(0xFFFFFFFFu, nz);
            if (tid == 0) g_idx64 = (m == 0u) ? 1 : 0;
        }
    }
}

// ---------------- adjacency build --------------------------------
__global__ void fill_kernel(const void* __restrict__ eidx, int E) {
    const int is64 = g_idx64;
    int i = blockIdx.x * blockDim.x + threadIdx.x;
    if (i < E) {
        int s, t;
        if (is64) {
            s = (int)((const long long*)eidx)[i];
            t = (int)((const long long*)eidx)[(long long)E + i];
        } else {
            s = ((const int*)eidx)[i];
            t = ((const int*)eidx)[E + i];
        }
        int p = atomicAdd(&g_cursor[t], 1);
        if (p < CAP) g_srcs[t * CAP + p] = s;
    }
}

// ---- per-edge weights, once: g_w[n*CAP+j] = dinv[src]*dinv[n] ----
__global__ __launch_bounds__(256) void edge_w_kernel(int N) {
    const int n = (int)((blockIdx.x * blockDim.x + threadIdx.x) >> 5);
    if (n >= N) return;
    const int lane = threadIdx.x & 31;
    const int cnt = min(g_cursor[n], CAP);
    const float dn = rsqrtf((float)cnt + 1.0f);
    for (int j = lane; j < cnt; j += 32) {
        int s = g_srcs[n * CAP + j];
        g_w[n * CAP + j] = rsqrtf((float)min(g_cursor[s], CAP) + 1.0f) * dn;
    }
}

// ---------------- bf16 tensor-core GEMM (A bf16/fp32, W hi+lo bf16) ------
// out_bf16[M,128] = op(A)[M,128] @ W[128,128] (+ epi_bias)
//   PRO:   op(a)[r][c] = relu(a[r][c] + pro_bias[c])
//   ABF16: A is bf16 (g_ab); else fp32
// 256 threads = 8 warps (4M x 2N), warp tile 32x64. 2 CTAs/SM.
// Each B fragment LDS.128 feeds 2 M-blocks -> 0.5 LDS/MMA.
template<bool PRO, bool ABF16>
__global__ __launch_bounds__(256, 2) void gemm_kernel(
    const void* Aptr, int widx,
    const float* __restrict__ pro_bias, const float* __restrict__ epi_bias,
    __nv_bfloat162* __restrict__ outB, int M)
{
    extern __shared__ uint4 smem_u4[];
    uint4* Bs = smem_u4;                              // [8][16][32] uint4
    uint32_t* As = (uint32_t*)(smem_u4 + BFRAG_PER_W);// [128][SAB] bf16x2

    const int tid = threadIdx.x;
    const int row0 = blockIdx.x * 128;

    // ---- load packed B frags (64KB) ----
    {
        const uint4* src = g_Bfrag + (size_t)widx * BFRAG_PER_W;
#pragma unroll
        for (int l = 0; l < BFRAG_PER_W / 256; l++)
            Bs[tid + l * 256] = src[tid + l * 256];
    }
    // ---- load A tile (optional fused bias+relu) into bf16x2 smem ----
    if (ABF16) {
        const uint4* A4 = (const uint4*)Aptr;   // 8 bf16 per uint4, 16/row
#pragma unroll
        for (int l = 0; l < 8; l++) {
            int f = tid + l * 256;               // 0..2047 uint4 slots
            int r = f >> 4;
            int c4 = f & 15;                     // uint4 col (8 bf16)
            int grow = row0 + r;
            uint4 u = make_uint4(0, 0, 0, 0);
            if (grow < M) {
                u = A4[(size_t)grow * 16 + c4];
                if (PRO) {
                    const float4 b0 = ((const float4*)pro_bias)[c4 * 2];
                    const float4 b1 = ((const float4*)pro_bias)[c4 * 2 + 1];
                    float2 p;
                    p = unpack_bf16x2(u.x);
                    u.x = pack_bf16x2(fmaxf(p.x + b0.x, 0.f), fmaxf(p.y + b0.y, 0.f));
                    p = unpack_bf16x2(u.y);
                    u.y = pack_bf16x2(fmaxf(p.x + b0.z, 0.f), fmaxf(p.y + b0.w, 0.f));
                    p = unpack_bf16x2(u.z);
                    u.z = pack_bf16x2(fmaxf(p.x + b1.x, 0.f), fmaxf(p.y + b1.y, 0.f));
                    p = unpack_bf16x2(u.w);
                    u.w = pack_bf16x2(fmaxf(p.x + b1.z, 0.f), fmaxf(p.y + b1.w, 0.f));
                }
            }
            uint32_t* dst = &As[r * SAB + c4 * 4];
            dst[0] = u.x; dst[1] = u.y; dst[2] = u.z; dst[3] = u.w;
        }
    } else {
        const float* A = (const float*)Aptr;
#pragma unroll
        for (int l = 0; l < 16; l++) {
            int f = tid + l * 256;               // 0..4095 float4 slots
            int r = f >> 5;
            int c4 = f & 31;
            int grow = row0 + r;
            float4 v = make_float4(0.f, 0.f, 0.f, 0.f);
            if (grow < M)
                v = *(const float4*)&A[(size_t)grow * 128 + c4 * 4];
            As[r * SAB + c4 * 2]     = pack_bf16x2(v.x, v.y);
            As[r * SAB + c4 * 2 + 1] = pack_bf16x2(v.z, v.w);
        }
    }
    __syncthreads();

    const int warp = tid >> 5;
    const int lane = tid & 31;
    const int g = lane >> 2;
    const int t = lane & 3;
    const int wm = (warp >> 1) * 32;   // 4 M-warps, 32 rows each
    const int jnb = (warp & 1) * 8;    // 2 N-warps, 8 n-blocks each

    float C[2][8][4];
#pragma unroll
    for (int i = 0; i < 2; i++)
#pragma unroll
        for (int j = 0; j < 8; j++)
#pragma unroll
            for (int q = 0; q < 4; q++) C[i][j][q] = 0.0f;

#pragma unroll
    for (int kb = 0; kb < 8; kb++) {
        uint32_t a[2][4];
#pragma unroll
        for (int i = 0; i < 2; i++) {
            const int rb = wm + i * 16;
            a[i][0] = As[(rb + g) * SAB + kb * 8 + t];
            a[i][1] = As[(rb + 8 + g) * SAB + kb * 8 + t];
            a[i][2] = As[(rb + g) * SAB + kb * 8 + t + 4];
            a[i][3] = As[(rb + 8 + g) * SAB + kb * 8 + t + 4];
        }
#pragma unroll
        for (int j = 0; j < 8; j++) {
            uint4 bf = Bs[(kb * 16 + jnb + j) * 32 + lane];
#pragma unroll
            for (int i = 0; i < 2; i++) {
                mma_bf16(C[i][j][0], C[i][j][1], C[i][j][2], C[i][j][3],
                         a[i][0], a[i][1], a[i][2], a[i][3], bf.x, bf.y);
                mma_bf16(C[i][j][0], C[i][j][1], C[i][j][2], C[i][j][3],
                         a[i][0], a[i][1], a[i][2], a[i][3], bf.z, bf.w);
            }
        }
    }

    // ---- epilogue: bf16x2 out (+ optional bias) ----
#pragma unroll
    for (int i = 0; i < 2; i++) {
#pragma unroll
        for (int j = 0; j < 8; j++) {
            const int col = (jnb + j) * 8 + 2 * t;
            float be0 = 0.f, be1 = 0.f;
            if (epi_bias) { be0 = epi_bias[col]; be1 = epi_bias[col + 1]; }
            const int r0 = row0 + wm + i * 16 + g;
            const int r1 = r0 + 8;
            if (r0 < M)
                outB[(size_t)r0 * (HID / 2) + (col >> 1)] =
                    __float22bfloat162_rn(make_float2(C[i][j][0] + be0, C[i][j][1] + be1));
            if (r1 < M)
                outB[(size_t)r1 * (HID / 2) + (col >> 1)] =
                    __float22bfloat162_rn(make_float2(C[i][j][2] + be0, C[i][j][3] + be1));
        }
    }
}

// ---------------- pull aggregation: warp = node, 2 edges in parallel -----
// Reads bf16 messages g_tb; writes bf16 activations g_ab.
__device__ __forceinline__ void unpack8(uint4 u, float* f) {
    float2 t0 = __bfloat1622float2(*(__nv_bfloat162*)&u.x);
    float2 t1 = __bfloat1622float2(*(__nv_bfloat162*)&u.y);
    float2 t2 = __bfloat1622float2(*(__nv_bfloat162*)&u.z);
    float2 t3 = __bfloat1622float2(*(__nv_bfloat162*)&u.w);
    f[0] = t0.x; f[1] = t0.y; f[2] = t1.x; f[3] = t1.y;
    f[4] = t2.x; f[5] = t2.y; f[6] = t3.x; f[7] = t3.y;
}

__global__ __launch_bounds__(256) void gather_kernel(int N) {
    const int n = (int)((blockIdx.x * blockDim.x + threadIdx.x) >> 5);
    if (n >= N) return;
    const int lane = threadIdx.x & 31;
    const int half = lane >> 4;       // 0 / 1: pair-slot parity
    const int fl = lane & 15;         // 16B feature chunk (8 bf16)
    const uint4* __restrict__ T4 = (const uint4*)g_tb;

    const int cnt = min(g_cursor[n], CAP);
    const float dn = rsqrtf((float)cnt + 1.0f);

    float acc[8];
    {   // self-loop added by half 0 only
        uint4 u = __ldg(&T4[(size_t)n * 16 + fl]);
        float f[8]; unpack8(u, f);
        const float s2 = half ? 0.0f : dn * dn;
#pragma unroll
        for (int k = 0; k < 8; k++) acc[k] = f[k] * s2;
    }

    const int base = n * CAP;
    for (int j0 = 0; j0 < cnt; j0 += 32) {
        const int m = min(32, cnt - j0);          // uniform across warp
        int   s_l = 0;                            // padding: row 0
        float w_l = 0.f;                          // padding: weight 0
        if (lane < m) {
            s_l = g_srcs[base + j0 + lane];
            w_l = g_w[base + j0 + lane];
        }
        const int npairs4 = ((((m + 1) >> 1) + 3) & ~3);   // <= 16
        for (int p = 0; p < npairs4; p += 4) {
            int ia = 2 * p + half;
            int ib = ia + 2, ic = ia + 4, id = ia + 6;
            int   sa = __shfl_sync(0xFFFFFFFFu, s_l, ia);
            int   sb = __shfl_sync(0xFFFFFFFFu, s_l, ib);
            int   sc = __shfl_sync(0xFFFFFFFFu, s_l, ic);
            int   sd = __shfl_sync(0xFFFFFFFFu, s_l, id);
            float na = __shfl_sync(0xFFFFFFFFu, w_l, ia);
            float nb = __shfl_sync(0xFFFFFFFFu, w_l, ib);
            float nc = __shfl_sync(0xFFFFFFFFu, w_l, ic);
            float nd = __shfl_sync(0xFFFFFFFFu, w_l, id);
            uint4 ua = __ldg(&T4[(size_t)sa * 16 + fl]);
            uint4 ub = __ldg(&T4[(size_t)sb * 16 + fl]);
            uint4 uc = __ldg(&T4[(size_t)sc * 16 + fl]);
            uint4 ud = __ldg(&T4[(size_t)sd * 16 + fl]);
            float fa[8], fb[8], fc[8], fd[8];
            unpack8(ua, fa); unpack8(ub, fb); unpack8(uc, fc); unpack8(ud, fd);
#pragma unroll
            for (int k = 0; k < 8; k++) {
                acc[k] = fmaf(na, fa[k], acc[k]);
                acc[k] = fmaf(nb, fb[k], acc[k]);
                acc[k] = fmaf(nc, fc[k], acc[k]);
                acc[k] = fmaf(nd, fd[k], acc[k]);
            }
        }
    }

#pragma unroll
    for (int k = 0; k < 8; k++)
        acc[k] += __shfl_xor_sync(0xFFFFFFFFu, acc[k], 16);

    // bf16 write: half 0 -> features fl*8..+3, half 1 -> fl*8+4..+7
    uint2 o;
    if (half) {
        o.x = pack_bf16x2(acc[4], acc[5]);
        o.y = pack_bf16x2(acc[6], acc[7]);
    } else {
        o.x = pack_bf16x2(acc[0], acc[1]);
        o.y = pack_bf16x2(acc[2], acc[3]);
    }
    ((uint2*)g_ab)[(size_t)n * 32 + fl * 2 + half] = o;
}

// ---------------- mean pool, 2-stage (batch sorted), fused bias+relu -----
__device__ __forceinline__ int lower_bound_batch(const void* batch, int n, int val, int is64) {
    int lo = 0, hi = n;
    while (lo < hi) {
        int mid = (lo + hi) >> 1;
        long long b = is64 ? ((const long long*)batch)[mid]
                           : (long long)((const int*)batch)[mid];
        if (b < val) lo = mid + 1; else hi = mid;
    }
    return lo;
}

__global__ void pool_partial_kernel(const void* __restrict__ batch,
                                    const float* __restrict__ bias, int n) {
    const int g = blockIdx.x;
    const int sub = blockIdx.y;
    const int tid = threadIdx.x;
    __shared__ int slo, shi;
    if (tid == 0) {
        int is64 = g_idx64;
        slo = lower_bound_batch(batch, n, g, is64);
        shi = lower_bound_batch(batch, n, g + 1, is64);
    }
    __syncthreads();
    const float b = bias[tid];
    const __nv_bfloat16* __restrict__ ab = (const __nv_bfloat16*)g_ab;
    const int lo = slo, hi = shi;
    float s0 = 0.f, s1 = 0.f;
    int r = lo + sub;
    for (; r + NSUB < hi; r += 2 * NSUB) {
        s0 += fmaxf(__bfloat162float(ab[(size_t)r * HID + tid]) + b, 0.0f);
        s1 += fmaxf(__bfloat162float(ab[(size_t)(r + NSUB) * HID + tid]) + b, 0.0f);
    }
    if (r < hi)
        s0 += fmaxf(__bfloat162float(ab[(size_t)r * HID + tid]) + b, 0.0f);
    atomicAdd(&g_pooled[g * HID + tid], s0 + s1);
    if (sub == 0 && tid == 0) g_cnt[g] = (float)(hi - lo);
}

// ---------------- heads (divide pooled sum by count here) ----------------
__global__ void heads_kernel(
    const float* __restrict__ Wd, const float* __restrict__ bd,
    const float* __restrict__ Ws, const float* __restrict__ bsn,
    const float* __restrict__ Wr, const float* __restrict__ br,
    float* __restrict__ out)
{
    const int g = blockIdx.x;
    const int head = blockIdx.y;
    const int j = threadIdx.x;
    __shared__ float p[HID];
    const float inv = 1.0f / fmaxf(g_cnt[g], 1.0f);
    p[j] = g_pooled[g * HID + j] * inv;
    __syncthreads();

    const float* W = (head == 0) ? Wd : (head == 1) ? Ws : Wr;
    const float* b = (head == 0) ? bd : (head == 1) ? bsn : br;
    float s = b[j];
#pragma unroll 8
    for (int k = 0; k < HID; k++)
        s = fmaf(p[k], W[k * HID + j], s);
    out[(size_t)head * NGRAPH * HID + g * HID + j] = s;
}

// ---------------- launch --------------------------------------------------
extern "C" void kernel_launch(void* const* d_in, const int* in_sizes, int n_in,
                              void* d_out, int out_size)
{
    const float* x      = (const float*)d_in[0];
    const void*  eidx   = d_in[1];
    const void*  batch  = d_in[2];
    const float* W_in   = (const float*)d_in[3];
    const float* b_in   = (const float*)d_in[4];
    const float* conv_W = (const float*)d_in[5];
    const float* conv_b = (const float*)d_in[6];
    const float* W_def  = (const float*)d_in[7];
    const float* b_def  = (const float*)d_in[8];
    const float* W_syn  = (const float*)d_in[9];
    const float* b_syn  = (const float*)d_in[10];
    const float* W_rel  = (const float*)d_in[11];
    const float* b_rel  = (const float*)d_in[12];
    float* out = (float*)d_out;

    const int N = in_sizes[0] / HID;       // 50000
    const int E = in_sizes[1] / 2;         // 640000

    void *pab, *ptb, *pz;
    cudaGetSymbolAddress(&pab, g_ab);
    cudaGetSymbolAddress(&ptb, g_tb);
    cudaGetSymbolAddress(&pz, g_zero_bias);
    __nv_bfloat162* ab_buf = (__nv_bfloat162*)pab;
    __nv_bfloat162* tb_buf = (__nv_bfloat162*)ptb;
    const float* zero_b = (const float*)pz;

    static int smem_set = 0;
    if (!smem_set) {
        cudaFuncSetAttribute((const void*)gemm_kernel<false, false>,
                             cudaFuncAttributeMaxDynamicSharedMemorySize, SMEM_GEMM);
        cudaFuncSetAttribute((const void*)gemm_kernel<true, true>,
                             cudaFuncAttributeMaxDynamicSharedMemorySize, SMEM_GEMM);
        smem_set = 1;
    }

    const int T = 256;
    const int GB = (N + 127) / 128;
    const int GW = (N * 32 + T - 1) / T;   // warp-per-node grids

    // 0. fused setup: pack weights + zero cursors/pooled + dtype detect
    setup_kernel<<<SETUP_BLKS, T>>>(W_in, conv_W, (const int*)eidx);

    // 1. adjacency build
    fill_kernel<<<(E + T - 1) / T, T>>>(eidx, E);
    edge_w_kernel<<<GW, T>>>(N);

    // 2. input layer: ab = bf16(x @ W_in + b_in)  (pre-activation)
    gemm_kernel<false, false><<<GB, 256, SMEM_GEMM>>>(
        x, 0, nullptr, b_in, ab_buf, N);

    // 3. GCN layers: GEMM (relu+bias fused, bf16 in/out) then pull-gather
    for (int l = 0; l < NLAYERS; l++) {
        const float* pro_b = (l == 0) ? zero_b : conv_b + (size_t)(l - 1) * HID;
        gemm_kernel<true, true><<<GB, 256, SMEM_GEMM>>>(
            ab_buf, 1 + l, pro_b, nullptr, tb_buf, N);
        gather_kernel<<<GW, T>>>(N);
    }

    // 4. global mean pool (2-stage, fused final bias+relu)
    pool_partial_kernel<<<dim3(NGRAPH, NSUB), HID>>>(
        batch, conv_b + (size_t)(NLAYERS - 1) * HID, N);

    // 5. output heads
    heads_kernel<<<dim3(NGRAPH, 3), HID>>>(W_def, b_def, W_syn, b_syn,
                                           W_rel, b_rel, out);
}